// round 4
// baseline (speedup 1.0000x reference)
#include <cuda_runtime.h>
#include <math.h>

#define N_TS 8192
#define N_LC 12288
#define NB   64
#define TSB  128
#define LCB  192
#define H    16
#define ROWP 20      // padded smem row stride (floats) -> conflict-free quad reads

// ---------------- scratch ----------------
__device__ float g_ts_enc[N_TS * H];
__device__ float g_u_ts [N_TS * H];
__device__ float g_lc_enc[N_LC * H];
__device__ float g_u_lc [N_LC * H];
__device__ float g_v_lc [N_LC * H];
__device__ float g_nrm_lc[N_LC];
__device__ float g_f1  [N_LC * H];
__device__ float g_v3  [N_LC * H];
__device__ float g_nrm3[N_LC];
__device__ float g_f2  [N_TS * H];
__device__ float g_u3  [N_TS * H];
__device__ float g_f3  [N_TS * H];

__device__ __forceinline__ float eluf(float x) { return x > 0.f ? x : expm1f(x); }

__device__ __forceinline__ void ld16s(float (&x)[H], const float* p) {
    const float4* p4 = (const float4*)p;
    #pragma unroll
    for (int q = 0; q < 4; q++) {
        float4 v = p4[q];
        x[4*q] = v.x; x[4*q+1] = v.y; x[4*q+2] = v.z; x[4*q+3] = v.w;
    }
}
__device__ __forceinline__ void ld16g(float (&x)[H], const float* p) {
    const float4* p4 = (const float4*)p;
    #pragma unroll
    for (int q = 0; q < 4; q++) {
        float4 v = __ldg(&p4[q]);
        x[4*q] = v.x; x[4*q+1] = v.y; x[4*q+2] = v.z; x[4*q+3] = v.w;
    }
}

// distance with pinned arithmetic tree (must be bit-identical pass1 vs pass2)
__device__ __forceinline__ float distf(const float (&xi)[H], float nd,
                                       const float* __restrict__ sp, float nj)
{
    const float4* p4 = (const float4*)sp;
    float4 p0 = p4[0], p1 = p4[1], p2 = p4[2], p3 = p4[3];
    float d0 = fmaf(xi[0],  p0.x, fmaf(xi[1],  p0.y, fmaf(xi[2],  p0.z, xi[3]  * p0.w)));
    float d1 = fmaf(xi[4],  p1.x, fmaf(xi[5],  p1.y, fmaf(xi[6],  p1.z, xi[7]  * p1.w)));
    float d2 = fmaf(xi[8],  p2.x, fmaf(xi[9],  p2.y, fmaf(xi[10], p2.z, xi[11] * p2.w)));
    float d3 = fmaf(xi[12], p3.x, fmaf(xi[13], p3.y, fmaf(xi[14], p3.z, xi[15] * p3.w)));
    float dot = __fadd_rn(__fadd_rn(d0, d1), __fadd_rn(d2, d3));
    return fmaf(-2.0f, dot, __fadd_rn(nd, nj));
}

// 4 threads per dst (quad = t&3), each scans candidates j*4+quad, j=0..47.
// Exact top-16 threshold via sorted lists + bitonic merges; then threshold re-scan
// accumulating channelwise max of v over the selected set.
__device__ __forceinline__ void knn_maxv(const float (&xi)[H], float nd,
                                         const float* __restrict__ s_enc,
                                         const float* __restrict__ s_v,
                                         const float* __restrict__ s_nrm,
                                         int quad, float (&mv)[H])
{
    // ---- pass 1: sorted-16 of my 48 distances (branchless min/max chain) ----
    float bd[16];
    #pragma unroll
    for (int k = 0; k < 16; k++) bd[k] = 1e30f;
    for (int j = 0; j < 48; j++) {
        int row = (j << 2) | quad;
        float d = distf(xi, nd, s_enc + row * ROWP, s_nrm[row]);
        #pragma unroll
        for (int k = 0; k < 16; k++) {
            float lo = fminf(d, bd[k]);
            d = fmaxf(d, bd[k]);
            bd[k] = lo;
        }
    }
    // ---- merge with xor1 partner: min-pair -> bitonic -> sort ----
    float m[16];
    #pragma unroll
    for (int k = 0; k < 16; k++) {
        float ob = __shfl_xor_sync(0xFFFFFFFFu, bd[15 - k], 1);
        m[k] = fminf(bd[k], ob);       // ascending-then-descending (bitonic)
    }
    #pragma unroll
    for (int j = 8; j > 0; j >>= 1) {
        #pragma unroll
        for (int i = 0; i < 16; i++) {
            if ((i & j) == 0) {
                float lo = fminf(m[i], m[i + j]);
                float hi = fmaxf(m[i], m[i + j]);
                m[i] = lo; m[i + j] = hi;
            }
        }
    }
    // ---- merge with xor2 partner-pair: T = 16th smallest of all 192 ----
    float T = -1e30f;
    #pragma unroll
    for (int k = 0; k < 16; k++) {
        float ob = __shfl_xor_sync(0xFFFFFFFFu, m[15 - k], 2);
        T = fmaxf(T, fminf(m[k], ob));
    }
    // ---- pass 2: rescan, fmax v over selected ----
    #pragma unroll
    for (int k = 0; k < 16; k++) mv[k] = -1e30f;
    for (int j = 0; j < 48; j++) {
        int row = (j << 2) | quad;
        float d = distf(xi, nd, s_enc + row * ROWP, s_nrm[row]);
        if (d <= T) {
            const float4* v4 = (const float4*)(s_v + row * ROWP);
            float4 q0 = v4[0], q1 = v4[1], q2 = v4[2], q3 = v4[3];
            mv[0]  = fmaxf(mv[0],  q0.x); mv[1]  = fmaxf(mv[1],  q0.y);
            mv[2]  = fmaxf(mv[2],  q0.z); mv[3]  = fmaxf(mv[3],  q0.w);
            mv[4]  = fmaxf(mv[4],  q1.x); mv[5]  = fmaxf(mv[5],  q1.y);
            mv[6]  = fmaxf(mv[6],  q1.z); mv[7]  = fmaxf(mv[7],  q1.w);
            mv[8]  = fmaxf(mv[8],  q2.x); mv[9]  = fmaxf(mv[9],  q2.y);
            mv[10] = fmaxf(mv[10], q2.z); mv[11] = fmaxf(mv[11], q2.w);
            mv[12] = fmaxf(mv[12], q3.x); mv[13] = fmaxf(mv[13], q3.y);
            mv[14] = fmaxf(mv[14], q3.z); mv[15] = fmaxf(mv[15], q3.w);
        }
    }
    #pragma unroll
    for (int k = 0; k < 16; k++) mv[k] = fmaxf(mv[k], __shfl_xor_sync(0xFFFFFFFFu, mv[k], 1));
    #pragma unroll
    for (int k = 0; k < 16; k++) mv[k] = fmaxf(mv[k], __shfl_xor_sync(0xFFFFFFFFu, mv[k], 2));
}

// ==================== K1: encoders + u/v/nrm precompute ====================
__global__ void k_encode(const float* __restrict__ x_ts, const float* __restrict__ x_lc,
                         const float* __restrict__ tw1, const float* __restrict__ tb1,
                         const float* __restrict__ tw2, const float* __restrict__ tb2,
                         const float* __restrict__ lw1, const float* __restrict__ lb1,
                         const float* __restrict__ lw2, const float* __restrict__ lb2,
                         const float* __restrict__ cw,  const float* __restrict__ cb)
{
    int tid = blockIdx.x * blockDim.x + threadIdx.x;
    if (tid < N_TS) {
        float x[6], h1[H], e[H];
        #pragma unroll
        for (int i = 0; i < 6; i++) x[i] = __ldg(&x_ts[tid * 6 + i]);
        #pragma unroll
        for (int o = 0; o < H; o++) {
            float s = __ldg(&tb1[o]);
            #pragma unroll
            for (int i = 0; i < 6; i++) s += x[i] * __ldg(&tw1[i * H + o]);
            h1[o] = eluf(s);
        }
        #pragma unroll
        for (int o = 0; o < H; o++) {
            float s = __ldg(&tb2[o]);
            #pragma unroll
            for (int i = 0; i < H; i++) s += h1[i] * __ldg(&tw2[i * H + o]);
            e[o] = eluf(s);
            g_ts_enc[tid * H + o] = e[o];
        }
        #pragma unroll
        for (int o = 0; o < H; o++) {
            float s = __ldg(&cb[o]);
            #pragma unroll
            for (int i = 0; i < H; i++)
                s += e[i] * (__ldg(&cw[i * H + o]) - __ldg(&cw[(H + i) * H + o]));
            g_u_ts[tid * H + o] = s;
        }
    } else if (tid < N_TS + N_LC) {
        int id = tid - N_TS;
        float x[5], h1[H], e[H];
        #pragma unroll
        for (int i = 0; i < 5; i++) x[i] = __ldg(&x_lc[id * 5 + i]);
        #pragma unroll
        for (int o = 0; o < H; o++) {
            float s = __ldg(&lb1[o]);
            #pragma unroll
            for (int i = 0; i < 5; i++) s += x[i] * __ldg(&lw1[i * H + o]);
            h1[o] = eluf(s);
        }
        #pragma unroll
        for (int o = 0; o < H; o++) {
            float s = __ldg(&lb2[o]);
            #pragma unroll
            for (int i = 0; i < H; i++) s += h1[i] * __ldg(&lw2[i * H + o]);
            e[o] = eluf(s);
            g_lc_enc[id * H + o] = e[o];
        }
        float nrm = 0.f;
        #pragma unroll
        for (int o = 0; o < H; o++) nrm += e[o] * e[o];
        g_nrm_lc[id] = nrm;
        #pragma unroll
        for (int o = 0; o < H; o++) {
            float su = __ldg(&cb[o]), sv = 0.f;
            #pragma unroll
            for (int i = 0; i < H; i++) {
                float wt = __ldg(&cw[i * H + o]);
                float wb = __ldg(&cw[(H + i) * H + o]);
                su += e[i] * (wt - wb);
                sv += e[i] * wb;
            }
            g_u_lc[id * H + o] = su;
            g_v_lc[id * H + o] = sv;
        }
    }
}

// ==================== K2: conv1 (LC dst) + conv2 (TS dst) ====================
__global__ void __launch_bounds__(256)
k_conv12(const float* __restrict__ cw, const float* __restrict__ cb)
{
    __shared__ float s_enc[LCB * ROWP];
    __shared__ float s_v  [LCB * ROWP];
    __shared__ float s_nrm[LCB];
    __shared__ float s_w  [2 * H * H];
    __shared__ float s_b  [H];
    const int g = blockIdx.x / 5, part = blockIdx.x % 5;
    const int t = threadIdx.x;

    {
        const float4* ge = (const float4*)(g_lc_enc + g * LCB * H);
        const float4* gv = (const float4*)(g_v_lc  + g * LCB * H);
        float4* se = (float4*)s_enc; float4* sv = (float4*)s_v;
        #pragma unroll
        for (int i = t; i < LCB * 4; i += 256) {
            int r = i >> 2, c = i & 3;
            se[r * 5 + c] = ge[i];
            sv[r * 5 + c] = gv[i];
        }
        if (t < LCB) s_nrm[t] = g_nrm_lc[g * LCB + t];
        for (int i = t; i < 2 * H * H; i += 256) s_w[i] = __ldg(&cw[i]);
        if (t < H) s_b[t] = __ldg(&cb[t]);
    }
    __syncthreads();

    const int dl = t >> 2, quad = t & 3;
    const bool isLC = part < 3;
    const int dstRow = isLC ? g * LCB + part * 64 + dl
                            : g * TSB + (part - 3) * 64 + dl;
    float xi[H];
    if (isLC) ld16s(xi, s_enc + (part * 64 + dl) * ROWP);
    else      ld16g(xi, g_ts_enc + dstRow * H);

    float n0 = fmaf(xi[0],  xi[0],  fmaf(xi[1],  xi[1],  fmaf(xi[2],  xi[2],  xi[3]  * xi[3])));
    float n1 = fmaf(xi[4],  xi[4],  fmaf(xi[5],  xi[5],  fmaf(xi[6],  xi[6],  xi[7]  * xi[7])));
    float n2 = fmaf(xi[8],  xi[8],  fmaf(xi[9],  xi[9],  fmaf(xi[10], xi[10], xi[11] * xi[11])));
    float n3 = fmaf(xi[12], xi[12], fmaf(xi[13], xi[13], fmaf(xi[14], xi[14], xi[15] * xi[15])));
    float nd = (n0 + n1) + (n2 + n3);

    float mv[H];
    knn_maxv(xi, nd, s_enc, s_v, s_nrm, quad, mv);

    float f[H];
    {
        float u[H];
        ld16g(u, (isLC ? g_u_lc : g_u_ts) + dstRow * H);
        #pragma unroll
        for (int h = 0; h < H; h++) f[h] = eluf(u[h] + mv[h]);
    }

    const int ob = quad * 4;
    if (isLC) {
        ((float4*)(g_f1 + dstRow * H))[quad] = make_float4(f[ob], f[ob+1], f[ob+2], f[ob+3]);
        float a0 = 0.f, a1 = 0.f, a2 = 0.f, a3 = 0.f;
        #pragma unroll
        for (int i = 0; i < H; i++) {
            float4 wb4 = *(const float4*)&s_w[(H + i) * H + ob];
            float fi = f[i];
            a0 = fmaf(fi, wb4.x, a0); a1 = fmaf(fi, wb4.y, a1);
            a2 = fmaf(fi, wb4.z, a2); a3 = fmaf(fi, wb4.w, a3);
        }
        ((float4*)(g_v3 + dstRow * H))[quad] = make_float4(a0, a1, a2, a3);
        if (quad == 0) {
            float nr = 0.f;
            #pragma unroll
            for (int i = 0; i < H; i++) nr += f[i] * f[i];
            g_nrm3[dstRow] = nr;
        }
    } else {
        ((float4*)(g_f2 + dstRow * H))[quad] = make_float4(f[ob], f[ob+1], f[ob+2], f[ob+3]);
        float a0 = s_b[ob], a1 = s_b[ob+1], a2 = s_b[ob+2], a3 = s_b[ob+3];
        #pragma unroll
        for (int i = 0; i < H; i++) {
            float4 wt4 = *(const float4*)&s_w[i * H + ob];
            float4 wb4 = *(const float4*)&s_w[(H + i) * H + ob];
            float fi = f[i];
            a0 = fmaf(fi, wt4.x - wb4.x, a0); a1 = fmaf(fi, wt4.y - wb4.y, a1);
            a2 = fmaf(fi, wt4.z - wb4.z, a2); a3 = fmaf(fi, wt4.w - wb4.w, a3);
        }
        ((float4*)(g_u3 + dstRow * H))[quad] = make_float4(a0, a1, a2, a3);
    }
}

// ==================== K3: conv3 (TS dst over feats1 src) ====================
__global__ void __launch_bounds__(256) k_conv3()
{
    __shared__ float s_enc[LCB * ROWP];
    __shared__ float s_v  [LCB * ROWP];
    __shared__ float s_nrm[LCB];
    const int g = blockIdx.x >> 1, half = blockIdx.x & 1;
    const int t = threadIdx.x;
    {
        const float4* ge = (const float4*)(g_f1 + g * LCB * H);
        const float4* gv = (const float4*)(g_v3 + g * LCB * H);
        float4* se = (float4*)s_enc; float4* sv = (float4*)s_v;
        #pragma unroll
        for (int i = t; i < LCB * 4; i += 256) {
            int r = i >> 2, c = i & 3;
            se[r * 5 + c] = ge[i];
            sv[r * 5 + c] = gv[i];
        }
        if (t < LCB) s_nrm[t] = g_nrm3[g * LCB + t];
    }
    __syncthreads();

    const int dl = t >> 2, quad = t & 3;
    const int dstRow = g * TSB + half * 64 + dl;
    float xi[H];
    ld16g(xi, g_f2 + dstRow * H);
    float n0 = fmaf(xi[0],  xi[0],  fmaf(xi[1],  xi[1],  fmaf(xi[2],  xi[2],  xi[3]  * xi[3])));
    float n1 = fmaf(xi[4],  xi[4],  fmaf(xi[5],  xi[5],  fmaf(xi[6],  xi[6],  xi[7]  * xi[7])));
    float n2 = fmaf(xi[8],  xi[8],  fmaf(xi[9],  xi[9],  fmaf(xi[10], xi[10], xi[11] * xi[11])));
    float n3 = fmaf(xi[12], xi[12], fmaf(xi[13], xi[13], fmaf(xi[14], xi[14], xi[15] * xi[15])));
    float nd = (n0 + n1) + (n2 + n3);

    float mv[H];
    knn_maxv(xi, nd, s_enc, s_v, s_nrm, quad, mv);

    float u[H];
    ld16g(u, g_u3 + dstRow * H);
    const int ob = quad * 4;
    float f0 = eluf(u[ob] + mv[ob]),     f1 = eluf(u[ob+1] + mv[ob+1]);
    float f2 = eluf(u[ob+2] + mv[ob+2]), f3 = eluf(u[ob+3] + mv[ob+3]);
    ((float4*)(g_f3 + dstRow * H))[quad] = make_float4(f0, f1, f2, f3);
}

// ==================== K4: mean pool + head ====================
__global__ void __launch_bounds__(128)
k_final(const float* __restrict__ w1, const float* __restrict__ b1,
        const float* __restrict__ w2, const float* __restrict__ b2,
        const float* __restrict__ w3, const float* __restrict__ b3,
        const float* __restrict__ w4, const float* __restrict__ b4,
        const float* __restrict__ w5, const float* __restrict__ b5,
        float* __restrict__ out, int out_size)
{
    __shared__ float sw1[H * 64], sw2[64 * 32], sw3[32 * 8], sw4[8 * 4], sw5[4];
    __shared__ float sb1[64], sb2[32], sb3[8], sb4[4], sb5;
    __shared__ float s_red[128];
    __shared__ float pooled[H];
    __shared__ float h1s[64], h2s[32], h3s[8], h4s[4];
    const int b = blockIdx.x, t = threadIdx.x;

    for (int i = t; i < H * 64; i += 128) sw1[i] = __ldg(&w1[i]);
    for (int i = t; i < 64 * 32; i += 128) sw2[i] = __ldg(&w2[i]);
    for (int i = t; i < 32 * 8; i += 128) sw3[i] = __ldg(&w3[i]);
    if (t < 32)  sw4[t] = __ldg(&w4[t]);
    if (t < 4)   sw5[t] = __ldg(&w5[t]);
    if (t < 64)  sb1[t] = __ldg(&b1[t]);
    if (t < 32)  sb2[t] = __ldg(&b2[t]);
    if (t < 8)   sb3[t] = __ldg(&b3[t]);
    if (t < 4)   sb4[t] = __ldg(&b4[t]);
    if (t == 0)  sb5 = __ldg(&b5[0]);

    // partial sums: channel c over 16 rows per group
    {
        const int c = t & 15, grp = t >> 4;
        const float* fp = g_f3 + (b * TSB + grp * 16) * H + c;
        float acc = 0.f;
        #pragma unroll
        for (int r = 0; r < 16; r++) acc += fp[r * H];
        s_red[t] = acc;
    }
    __syncthreads();
    if (t < H) {
        float acc = 0.f;
        #pragma unroll
        for (int gg = 0; gg < 8; gg++) acc += s_red[gg * 16 + t];
        pooled[t] = acc * (1.f / (float)TSB);
    }
    __syncthreads();

    if (t < 64) {
        float sv = sb1[t];
        #pragma unroll
        for (int i = 0; i < H; i++) sv += pooled[i] * sw1[i * 64 + t];
        h1s[t] = eluf(sv);
    }
    __syncthreads();
    if (t < 32) {
        float sv = sb2[t];
        #pragma unroll
        for (int i = 0; i < 64; i++) sv += h1s[i] * sw2[i * 32 + t];
        h2s[t] = eluf(sv);
    }
    __syncthreads();
    if (t < 8) {
        float sv = sb3[t];
        #pragma unroll
        for (int i = 0; i < 32; i++) sv += h2s[i] * sw3[i * 8 + t];
        h3s[t] = eluf(sv);
    }
    __syncthreads();
    if (t < 4) {
        float sv = sb4[t];
        #pragma unroll
        for (int i = 0; i < 8; i++) sv += h3s[i] * sw4[i * 4 + t];
        h4s[t] = eluf(sv);
    }
    __syncthreads();
    if (t == 0) {
        float sv = sb5;
        #pragma unroll
        for (int i = 0; i < 4; i++) sv += h4s[i] * sw5[i];
        if (b < out_size) out[b] = sv;
    }
    if (b == 0 && t < NB) {
        int idx = NB + t;
        if (idx < out_size) out[idx] = (float)t;
    }
}

// ==================== launch ====================
extern "C" void kernel_launch(void* const* d_in, const int* in_sizes, int n_in,
                              void* d_out, int out_size)
{
    const float* x_ts = (const float*)d_in[0];
    const float* x_lc = (const float*)d_in[1];
    const float* tw1 = (const float*)d_in[4];
    const float* tb1 = (const float*)d_in[5];
    const float* tw2 = (const float*)d_in[6];
    const float* tb2 = (const float*)d_in[7];
    const float* lw1 = (const float*)d_in[8];
    const float* lb1 = (const float*)d_in[9];
    const float* lw2 = (const float*)d_in[10];
    const float* lb2 = (const float*)d_in[11];
    const float* cw  = (const float*)d_in[12];
    const float* cb  = (const float*)d_in[13];
    const float* w1  = (const float*)d_in[14];
    const float* b1  = (const float*)d_in[15];
    const float* w2  = (const float*)d_in[16];
    const float* b2  = (const float*)d_in[17];
    const float* w3  = (const float*)d_in[18];
    const float* b3  = (const float*)d_in[19];
    const float* w4  = (const float*)d_in[20];
    const float* b4  = (const float*)d_in[21];
    const float* w5  = (const float*)d_in[22];
    const float* b5  = (const float*)d_in[23];

    k_encode<<<(N_TS + N_LC) / 128, 128>>>(x_ts, x_lc, tw1, tb1, tw2, tb2,
                                           lw1, lb1, lw2, lb2, cw, cb);
    k_conv12<<<NB * 5, 256>>>(cw, cb);
    k_conv3<<<NB * 2, 256>>>();
    k_final<<<NB, 128>>>(w1, b1, w2, b2, w3, b3, w4, b4, w5, b5,
                         (float*)d_out, out_size);
}

// round 6
// speedup vs baseline: 1.8505x; 1.8505x over previous
#include <cuda_runtime.h>
#include <math.h>

#define N_TS 8192
#define N_LC 12288
#define NB   64
#define TSB  128
#define LCB  192
#define H    16
#define ROWP 20

// ---------------- global scratch ----------------
__device__ float g_f1  [N_LC * H];
__device__ float g_v3  [N_LC * H];
__device__ float g_nrm3[N_LC];
__device__ float g_f2  [N_TS * H];
__device__ float g_u3  [N_TS * H];
__device__ float g_part[NB * 4 * H];
__device__ int   g_cnt [NB];

__device__ __forceinline__ float eluf(float x) { return x > 0.f ? x : expm1f(x); }

__device__ __forceinline__ void ld16g(float (&x)[H], const float* p) {
    const float4* p4 = (const float4*)p;
    #pragma unroll
    for (int q = 0; q < 4; q++) {
        float4 v = __ldg(&p4[q]);
        x[4*q] = v.x; x[4*q+1] = v.y; x[4*q+2] = v.z; x[4*q+3] = v.w;
    }
}
__device__ __forceinline__ void ld16s(float (&x)[H], const float* p) {
    const float4* p4 = (const float4*)p;
    #pragma unroll
    for (int q = 0; q < 4; q++) {
        float4 v = p4[q];
        x[4*q] = v.x; x[4*q+1] = v.y; x[4*q+2] = v.z; x[4*q+3] = v.w;
    }
}

__device__ __forceinline__ float distf(const float (&xi)[H], float nd,
                                       const float* __restrict__ sp, float nj)
{
    const float4* p4 = (const float4*)sp;
    float4 p0 = p4[0], p1 = p4[1], p2 = p4[2], p3 = p4[3];
    float d0 = fmaf(xi[0],  p0.x, fmaf(xi[1],  p0.y, fmaf(xi[2],  p0.z, xi[3]  * p0.w)));
    float d1 = fmaf(xi[4],  p1.x, fmaf(xi[5],  p1.y, fmaf(xi[6],  p1.z, xi[7]  * p1.w)));
    float d2 = fmaf(xi[8],  p2.x, fmaf(xi[9],  p2.y, fmaf(xi[10], p2.z, xi[11] * p2.w)));
    float d3 = fmaf(xi[12], p3.x, fmaf(xi[13], p3.y, fmaf(xi[14], p3.z, xi[15] * p3.w)));
    float dot = __fadd_rn(__fadd_rn(d0, d1), __fadd_rn(d2, d3));
    return fmaf(-2.0f, dot, __fadd_rn(nd, nj));
}

__device__ __forceinline__ float norm16(const float (&x)[H]) {
    float n0 = fmaf(x[0],  x[0],  fmaf(x[1],  x[1],  fmaf(x[2],  x[2],  x[3]  * x[3])));
    float n1 = fmaf(x[4],  x[4],  fmaf(x[5],  x[5],  fmaf(x[6],  x[6],  x[7]  * x[7])));
    float n2 = fmaf(x[8],  x[8],  fmaf(x[9],  x[9],  fmaf(x[10], x[10], x[11] * x[11])));
    float n3 = fmaf(x[12], x[12], fmaf(x[13], x[13], fmaf(x[14], x[14], x[15] * x[15])));
    return (n0 + n1) + (n2 + n3);
}

// pass1: compute + cache all 48 distances of this thread, keep sorted-16,
// merge across the quad (xor1 bitonic sort, xor2 min-pair+max) -> exact T.
template<int NT>
__device__ __forceinline__ float pass1_T(const float (&xi)[H], float nd,
                                         const float* __restrict__ s_enc,
                                         const float* __restrict__ s_nrm,
                                         float* __restrict__ s_d,
                                         int quad, int t)
{
    float bd[16];
    #pragma unroll
    for (int k = 0; k < 16; k++) bd[k] = 1e30f;
    #pragma unroll 2
    for (int j = 0; j < 48; j++) {
        int row = (j << 2) | quad;
        float d = distf(xi, nd, s_enc + row * ROWP, s_nrm[row]);
        s_d[j * NT + t] = d;
        #pragma unroll
        for (int k = 0; k < 16; k++) {
            float lo = fminf(d, bd[k]);
            d = fmaxf(d, bd[k]);
            bd[k] = lo;
        }
    }
    float m[16];
    #pragma unroll
    for (int k = 0; k < 16; k++) {
        float ob = __shfl_xor_sync(0xFFFFFFFFu, bd[15 - k], 1);
        m[k] = fminf(bd[k], ob);
    }
    #pragma unroll
    for (int j = 8; j > 0; j >>= 1) {
        #pragma unroll
        for (int i = 0; i < 16; i++) {
            if ((i & j) == 0) {
                float lo = fminf(m[i], m[i + j]);
                float hi = fmaxf(m[i], m[i + j]);
                m[i] = lo; m[i + j] = hi;
            }
        }
    }
    float T = -1e30f;
    #pragma unroll
    for (int k = 0; k < 16; k++) {
        float ob = __shfl_xor_sync(0xFFFFFFFFu, m[15 - k], 2);
        T = fmaxf(T, fminf(m[k], ob));
    }
    return T;
}

// pass2: compact selected (d<=T) via shared atomics, split v loads across quad,
// fmax-accumulate, quad-reduce via shfl. Order-independent -> deterministic.
template<int NT>
__device__ __forceinline__ void select_maxv(float T,
                                            const float* __restrict__ s_d,
                                            const float* __restrict__ s_v,
                                            int* __restrict__ s_cnt,
                                            int* __restrict__ s_sel,
                                            int dl, int quad, int t, float (&mv)[H])
{
    for (int j = 0; j < 48; j++) {
        float d = s_d[j * NT + t];
        if (d <= T) {
            int p = atomicAdd(&s_cnt[dl], 1);
            if (p < 24) s_sel[dl * 24 + p] = (j << 2) | quad;
        }
    }
    __syncwarp();
    #pragma unroll
    for (int h = 0; h < H; h++) mv[h] = -1e30f;
    int n = s_cnt[dl]; if (n > 24) n = 24;
    for (int k = quad; k < n; k += 4) {
        int row = s_sel[dl * 24 + k];
        const float4* v4 = (const float4*)(s_v + row * ROWP);
        float4 q0 = v4[0], q1 = v4[1], q2 = v4[2], q3 = v4[3];
        mv[0]  = fmaxf(mv[0],  q0.x); mv[1]  = fmaxf(mv[1],  q0.y);
        mv[2]  = fmaxf(mv[2],  q0.z); mv[3]  = fmaxf(mv[3],  q0.w);
        mv[4]  = fmaxf(mv[4],  q1.x); mv[5]  = fmaxf(mv[5],  q1.y);
        mv[6]  = fmaxf(mv[6],  q1.z); mv[7]  = fmaxf(mv[7],  q1.w);
        mv[8]  = fmaxf(mv[8],  q2.x); mv[9]  = fmaxf(mv[9],  q2.y);
        mv[10] = fmaxf(mv[10], q2.z); mv[11] = fmaxf(mv[11], q2.w);
        mv[12] = fmaxf(mv[12], q3.x); mv[13] = fmaxf(mv[13], q3.y);
        mv[14] = fmaxf(mv[14], q3.z); mv[15] = fmaxf(mv[15], q3.w);
    }
    #pragma unroll
    for (int h = 0; h < H; h++) mv[h] = fmaxf(mv[h], __shfl_xor_sync(0xFFFFFFFFu, mv[h], 1));
    #pragma unroll
    for (int h = 0; h < H; h++) mv[h] = fmaxf(mv[h], __shfl_xor_sync(0xFFFFFFFFu, mv[h], 2));
}

// ================= K_A: inline encode + conv1 + conv2 (+u3/v3 fused) =================
// smem layout (floats):
#define A_ENC 0
#define A_V   3840
#define A_NRM 7680
#define A_W   7872
#define A_B   8384
#define A_EW  8400
#define A_DST 9152
#define A_U   10176
#define A_D   11200
#define A_CNT 23488
#define A_SEL 23552
#define A_TOTF 25088   // 100352 bytes

__global__ void __launch_bounds__(256, 2)
kA(const float* __restrict__ x_ts, const float* __restrict__ x_lc,
   const float* __restrict__ tw1, const float* __restrict__ tb1,
   const float* __restrict__ tw2, const float* __restrict__ tb2,
   const float* __restrict__ lw1, const float* __restrict__ lb1,
   const float* __restrict__ lw2, const float* __restrict__ lb2,
   const float* __restrict__ cw,  const float* __restrict__ cb)
{
    extern __shared__ float sm[];
    float* s_enc = sm + A_ENC;
    float* s_v   = sm + A_V;
    float* s_nrm = sm + A_NRM;
    float* s_w   = sm + A_W;
    float* s_b   = sm + A_B;
    float* s_ew  = sm + A_EW;
    float* s_dst = sm + A_DST;
    float* s_u   = sm + A_U;
    float* s_d   = sm + A_D;
    int*   s_cnt = (int*)(sm + A_CNT);
    int*   s_sel = (int*)(sm + A_SEL);

    const int g = blockIdx.x / 5, part = blockIdx.x % 5;
    const int t = threadIdx.x;
    const bool isLC = part < 3;

    // ---- stage weights ----
    for (int i = t; i < 512; i += 256) s_w[i] = __ldg(&cw[i]);
    if (t < 16) s_b[t] = __ldg(&cb[t]);
    for (int i = t; i < 752; i += 256) {
        float val;
        if      (i < 96)  val = __ldg(&tw1[i]);
        else if (i < 112) val = __ldg(&tb1[i - 96]);
        else if (i < 368) val = __ldg(&tw2[i - 112]);
        else if (i < 384) val = __ldg(&tb2[i - 368]);
        else if (i < 464) val = __ldg(&lw1[i - 384]);
        else if (i < 480) val = __ldg(&lb1[i - 464]);
        else if (i < 736) val = __ldg(&lw2[i - 480]);
        else              val = __ldg(&lb2[i - 736]);
        s_ew[i] = val;
    }
    if (t < 64) s_cnt[t] = 0;
    __syncthreads();

    // ---- encode phase ----
    if (t < 192) {
        float x[5], h1[H], e[H];
        const float* xr = &x_lc[(g * LCB + t) * 5];
        #pragma unroll
        for (int i = 0; i < 5; i++) x[i] = __ldg(&xr[i]);
        #pragma unroll
        for (int o = 0; o < H; o++) {
            float sv = s_ew[464 + o];
            #pragma unroll
            for (int i = 0; i < 5; i++) sv += x[i] * s_ew[384 + i * H + o];
            h1[o] = eluf(sv);
        }
        #pragma unroll
        for (int o = 0; o < H; o++) {
            float sv = s_ew[736 + o];
            #pragma unroll
            for (int i = 0; i < H; i++) sv += h1[i] * s_ew[480 + i * H + o];
            e[o] = eluf(sv);
        }
        #pragma unroll
        for (int o = 0; o < H; o++) s_enc[t * ROWP + o] = e[o];
        s_nrm[t] = norm16(e);
        #pragma unroll
        for (int o = 0; o < H; o++) {
            float sv = 0.f;
            #pragma unroll
            for (int i = 0; i < H; i++) sv += e[i] * s_w[(H + i) * H + o];
            s_v[t * ROWP + o] = sv;
        }
        if (isLC && t >= part * 64 && t < part * 64 + 64) {
            int r = t - part * 64;
            #pragma unroll
            for (int o = 0; o < H; o++) {
                float su = s_b[o];
                #pragma unroll
                for (int i = 0; i < H; i++)
                    su += e[i] * (s_w[i * H + o] - s_w[(H + i) * H + o]);
                s_u[r * H + o] = su;
            }
        }
    } else if (!isLC) {
        int r = t - 192;
        int grow = g * TSB + (part - 3) * 64 + r;
        float x[6], h1[H], e[H];
        const float* xr = &x_ts[grow * 6];
        #pragma unroll
        for (int i = 0; i < 6; i++) x[i] = __ldg(&xr[i]);
        #pragma unroll
        for (int o = 0; o < H; o++) {
            float sv = s_ew[96 + o];
            #pragma unroll
            for (int i = 0; i < 6; i++) sv += x[i] * s_ew[i * H + o];
            h1[o] = eluf(sv);
        }
        #pragma unroll
        for (int o = 0; o < H; o++) {
            float sv = s_ew[368 + o];
            #pragma unroll
            for (int i = 0; i < H; i++) sv += h1[i] * s_ew[112 + i * H + o];
            e[o] = eluf(sv);
        }
        #pragma unroll
        for (int o = 0; o < H; o++) s_dst[r * H + o] = e[o];
        #pragma unroll
        for (int o = 0; o < H; o++) {
            float su = s_b[o];
            #pragma unroll
            for (int i = 0; i < H; i++)
                su += e[i] * (s_w[i * H + o] - s_w[(H + i) * H + o]);
            s_u[r * H + o] = su;
        }
    }
    __syncthreads();

    // ---- dst phase: 64 dst x 4 threads ----
    const int dl = t >> 2, quad = t & 3;
    float xi[H];
    if (isLC) ld16s(xi, s_enc + (part * 64 + dl) * ROWP);
    else      ld16s(xi, s_dst + dl * H);
    float nd = norm16(xi);

    float T = pass1_T<256>(xi, nd, s_enc, s_nrm, s_d, quad, t);
    float mv[H];
    select_maxv<256>(T, s_d, s_v, s_cnt, s_sel, dl, quad, t, mv);

    float f[H], u[H];
    ld16s(u, s_u + dl * H);
    #pragma unroll
    for (int h = 0; h < H; h++) f[h] = eluf(u[h] + mv[h]);

    const int ob = quad * 4;
    if (isLC) {
        int dstRow = g * LCB + part * 64 + dl;
        ((float4*)(g_f1 + dstRow * H))[quad] = make_float4(f[ob], f[ob+1], f[ob+2], f[ob+3]);
        float a0 = 0.f, a1 = 0.f, a2 = 0.f, a3 = 0.f;
        #pragma unroll
        for (int i = 0; i < H; i++) {
            float fi = f[i];
            a0 = fmaf(fi, s_w[(H + i) * H + ob + 0], a0);
            a1 = fmaf(fi, s_w[(H + i) * H + ob + 1], a1);
            a2 = fmaf(fi, s_w[(H + i) * H + ob + 2], a2);
            a3 = fmaf(fi, s_w[(H + i) * H + ob + 3], a3);
        }
        ((float4*)(g_v3 + dstRow * H))[quad] = make_float4(a0, a1, a2, a3);
        if (quad == 0) g_nrm3[dstRow] = norm16(f);
    } else {
        int dstRow = g * TSB + (part - 3) * 64 + dl;
        ((float4*)(g_f2 + dstRow * H))[quad] = make_float4(f[ob], f[ob+1], f[ob+2], f[ob+3]);
        float a0 = s_b[ob], a1 = s_b[ob+1], a2 = s_b[ob+2], a3 = s_b[ob+3];
        #pragma unroll
        for (int i = 0; i < H; i++) {
            float fi = f[i];
            a0 = fmaf(fi, s_w[i * H + ob + 0] - s_w[(H + i) * H + ob + 0], a0);
            a1 = fmaf(fi, s_w[i * H + ob + 1] - s_w[(H + i) * H + ob + 1], a1);
            a2 = fmaf(fi, s_w[i * H + ob + 2] - s_w[(H + i) * H + ob + 2], a2);
            a3 = fmaf(fi, s_w[i * H + ob + 3] - s_w[(H + i) * H + ob + 3], a3);
        }
        ((float4*)(g_u3 + dstRow * H))[quad] = make_float4(a0, a1, a2, a3);
    }
    // reset pool tickets for K_B (runs strictly after K_A in-stream)
    if (blockIdx.x < NB && t == 0) g_cnt[blockIdx.x] = 0;
}

// ================= K_B: conv3 + pool + head (last block of each graph) =================
// smem layout (floats):
#define B_ENC  0
#define B_V    3840
#define B_NRM  7680
#define B_D    7872
#define B_POOL 14016
#define B_PLD  14560
#define B_H1   14576
#define B_H2   14640
#define B_H3   14672
#define B_H4   14680
#define B_CNT  14684
#define B_SEL  14716
#define B_FLAG 15484
#define B_TOTF 15488   // 61952 bytes

__global__ void __launch_bounds__(128, 3)
kB(const float* __restrict__ w1, const float* __restrict__ b1,
   const float* __restrict__ w2, const float* __restrict__ b2,
   const float* __restrict__ w3, const float* __restrict__ b3,
   const float* __restrict__ w4, const float* __restrict__ b4,
   const float* __restrict__ w5, const float* __restrict__ b5,
   float* __restrict__ out, int out_size)
{
    extern __shared__ float sm[];
    float* s_enc  = sm + B_ENC;
    float* s_v    = sm + B_V;
    float* s_nrm  = sm + B_NRM;
    float* s_d    = sm + B_D;
    float* s_pool = sm + B_POOL;
    float* pooled = sm + B_PLD;
    float* h1s    = sm + B_H1;
    float* h2s    = sm + B_H2;
    float* h3s    = sm + B_H3;
    float* h4s    = sm + B_H4;
    int*   s_cnt  = (int*)(sm + B_CNT);
    int*   s_sel  = (int*)(sm + B_SEL);
    int*   s_flag = (int*)(sm + B_FLAG);

    const int g = blockIdx.x >> 2, qpart = blockIdx.x & 3;
    const int t = threadIdx.x;

    // stage feats1 / v3 / nrm3
    {
        const float4* ge = (const float4*)(g_f1 + g * LCB * H);
        const float4* gv = (const float4*)(g_v3 + g * LCB * H);
        float4* se = (float4*)s_enc; float4* sv = (float4*)s_v;
        #pragma unroll
        for (int i = t; i < LCB * 4; i += 128) {
            int r = i >> 2, c = i & 3;
            se[r * 5 + c] = __ldg(&ge[i]);
            sv[r * 5 + c] = __ldg(&gv[i]);
        }
        for (int i = t; i < LCB; i += 128) s_nrm[i] = __ldg(&g_nrm3[g * LCB + i]);
        if (t < 32) s_cnt[t] = 0;
    }
    __syncthreads();

    const int dl = t >> 2, quad = t & 3;
    const int dstRow = g * TSB + qpart * 32 + dl;
    float xi[H];
    ld16g(xi, g_f2 + dstRow * H);
    float nd = norm16(xi);

    float T = pass1_T<128>(xi, nd, s_enc, s_nrm, s_d, quad, t);
    float mv[H];
    select_maxv<128>(T, s_d, s_v, s_cnt, s_sel, dl, quad, t, mv);

    float u[H];
    ld16g(u, g_u3 + dstRow * H);
    const int ob = quad * 4;
    #pragma unroll
    for (int c = 0; c < 4; c++)
        s_pool[dl * 17 + ob + c] = eluf(u[ob + c] + mv[ob + c]);
    __syncthreads();

    if (t < H) {
        float a = 0.f;
        #pragma unroll
        for (int d = 0; d < 32; d++) a += s_pool[d * 17 + t];
        g_part[(g * 4 + qpart) * H + t] = a;
    }
    __threadfence();
    __syncthreads();
    if (t == 0) {
        int tk = atomicAdd(&g_cnt[g], 1);
        s_flag[0] = (tk == 3);
    }
    __syncthreads();

    if (s_flag[0]) {
        __threadfence();
        if (t < H) {
            float p01 = g_part[(g * 4 + 0) * H + t] + g_part[(g * 4 + 1) * H + t];
            float p23 = g_part[(g * 4 + 2) * H + t] + g_part[(g * 4 + 3) * H + t];
            pooled[t] = (p01 + p23) * (1.f / (float)TSB);
        }
        __syncthreads();
        if (t < 64) {
            float sv = __ldg(&b1[t]);
            #pragma unroll
            for (int i = 0; i < H; i++) sv += pooled[i] * __ldg(&w1[i * 64 + t]);
            h1s[t] = eluf(sv);
        }
        __syncthreads();
        if (t < 32) {
            float sv = __ldg(&b2[t]);
            #pragma unroll
            for (int i = 0; i < 64; i++) sv += h1s[i] * __ldg(&w2[i * 32 + t]);
            h2s[t] = eluf(sv);
        }
        __syncthreads();
        if (t < 8) {
            float sv = __ldg(&b3[t]);
            #pragma unroll
            for (int i = 0; i < 32; i++) sv += h2s[i] * __ldg(&w3[i * 8 + t]);
            h3s[t] = eluf(sv);
        }
        __syncthreads();
        if (t < 4) {
            float sv = __ldg(&b4[t]);
            #pragma unroll
            for (int i = 0; i < 8; i++) sv += h3s[i] * __ldg(&w4[i * 4 + t]);
            h4s[t] = eluf(sv);
        }
        __syncthreads();
        if (t == 0) {
            float sv = __ldg(&b5[0]);
            #pragma unroll
            for (int i = 0; i < 4; i++) sv += h4s[i] * __ldg(&w5[i]);
            if (g < out_size) out[g] = sv;
            if (NB + g < out_size) out[NB + g] = (float)g;  // batch_out tail
        }
    }
}

// ==================== launch ====================
extern "C" void kernel_launch(void* const* d_in, const int* in_sizes, int n_in,
                              void* d_out, int out_size)
{
    const float* x_ts = (const float*)d_in[0];
    const float* x_lc = (const float*)d_in[1];
    const float* tw1 = (const float*)d_in[4];
    const float* tb1 = (const float*)d_in[5];
    const float* tw2 = (const float*)d_in[6];
    const float* tb2 = (const float*)d_in[7];
    const float* lw1 = (const float*)d_in[8];
    const float* lb1 = (const float*)d_in[9];
    const float* lw2 = (const float*)d_in[10];
    const float* lb2 = (const float*)d_in[11];
    const float* cw  = (const float*)d_in[12];
    const float* cb  = (const float*)d_in[13];
    const float* w1  = (const float*)d_in[14];
    const float* b1  = (const float*)d_in[15];
    const float* w2  = (const float*)d_in[16];
    const float* b2  = (const float*)d_in[17];
    const float* w3  = (const float*)d_in[18];
    const float* b3  = (const float*)d_in[19];
    const float* w4  = (const float*)d_in[20];
    const float* b4  = (const float*)d_in[21];
    const float* w5  = (const float*)d_in[22];
    const float* b5  = (const float*)d_in[23];

    cudaFuncSetAttribute(kA, cudaFuncAttributeMaxDynamicSharedMemorySize, A_TOTF * 4);
    cudaFuncSetAttribute(kB, cudaFuncAttributeMaxDynamicSharedMemorySize, B_TOTF * 4);

    kA<<<NB * 5, 256, A_TOTF * 4>>>(x_ts, x_lc, tw1, tb1, tw2, tb2,
                                    lw1, lb1, lw2, lb2, cw, cb);
    kB<<<NB * 4, 128, B_TOTF * 4>>>(w1, b1, w2, b2, w3, b3, w4, b4, w5, b5,
                                    (float*)d_out, out_size);
}

// round 7
// speedup vs baseline: 2.0721x; 1.1197x over previous
#include <cuda_runtime.h>
#include <math.h>

#define N_TS 8192
#define N_LC 12288
#define NB   64
#define TSB  128
#define LCB  192
#define H    16
#define ROWP 20

// ---------------- global scratch ----------------
__device__ float g_ts_enc[N_TS * H];
__device__ float g_u_ts [N_TS * H];
__device__ float g_lc_enc[N_LC * H];
__device__ float g_u_lc [N_LC * H];
__device__ float g_v_lc [N_LC * H];
__device__ float g_nrm_lc[N_LC];
__device__ float g_f1  [N_LC * H];
__device__ float g_v3  [N_LC * H];
__device__ float g_nrm3[N_LC];
__device__ float g_f2  [N_TS * H];
__device__ float g_u3  [N_TS * H];
__device__ float g_part[NB * 8 * H];
__device__ int   g_cnt [NB];

__device__ __forceinline__ float eluf(float x) { return x > 0.f ? x : expm1f(x); }

__device__ __forceinline__ void ld16s(float (&x)[H], const float* p) {
    const float4* p4 = (const float4*)p;
    #pragma unroll
    for (int q = 0; q < 4; q++) {
        float4 v = p4[q];
        x[4*q] = v.x; x[4*q+1] = v.y; x[4*q+2] = v.z; x[4*q+3] = v.w;
    }
}
__device__ __forceinline__ void ld16g(float (&x)[H], const float* p) {
    const float4* p4 = (const float4*)p;
    #pragma unroll
    for (int q = 0; q < 4; q++) {
        float4 v = __ldg(&p4[q]);
        x[4*q] = v.x; x[4*q+1] = v.y; x[4*q+2] = v.z; x[4*q+3] = v.w;
    }
}

__device__ __forceinline__ float distf(const float (&xi)[H], float nd,
                                       const float* __restrict__ sp, float nj)
{
    const float4* p4 = (const float4*)sp;
    float4 p0 = p4[0], p1 = p4[1], p2 = p4[2], p3 = p4[3];
    float d0 = fmaf(xi[0],  p0.x, fmaf(xi[1],  p0.y, fmaf(xi[2],  p0.z, xi[3]  * p0.w)));
    float d1 = fmaf(xi[4],  p1.x, fmaf(xi[5],  p1.y, fmaf(xi[6],  p1.z, xi[7]  * p1.w)));
    float d2 = fmaf(xi[8],  p2.x, fmaf(xi[9],  p2.y, fmaf(xi[10], p2.z, xi[11] * p2.w)));
    float d3 = fmaf(xi[12], p3.x, fmaf(xi[13], p3.y, fmaf(xi[14], p3.z, xi[15] * p3.w)));
    float dot = __fadd_rn(__fadd_rn(d0, d1), __fadd_rn(d2, d3));
    return fmaf(-2.0f, dot, __fadd_rn(nd, nj));
}

__device__ __forceinline__ float norm16(const float (&x)[H]) {
    float n0 = fmaf(x[0],  x[0],  fmaf(x[1],  x[1],  fmaf(x[2],  x[2],  x[3]  * x[3])));
    float n1 = fmaf(x[4],  x[4],  fmaf(x[5],  x[5],  fmaf(x[6],  x[6],  x[7]  * x[7])));
    float n2 = fmaf(x[8],  x[8],  fmaf(x[9],  x[9],  fmaf(x[10], x[10], x[11] * x[11])));
    float n3 = fmaf(x[12], x[12], fmaf(x[13], x[13], fmaf(x[14], x[14], x[15] * x[15])));
    return (n0 + n1) + (n2 + n3);
}

// bitonic-merge-sort of a bitonic length-16 sequence -> ascending
__device__ __forceinline__ void bitonic16(float (&m)[16]) {
    #pragma unroll
    for (int j = 8; j > 0; j >>= 1) {
        #pragma unroll
        for (int i = 0; i < 16; i++) {
            if ((i & j) == 0) {
                float lo = fminf(m[i], m[i + j]);
                m[i + j] = fmaxf(m[i], m[i + j]);
                m[i] = lo;
            }
        }
    }
}

// 8 threads per dst (oct = t&7); thread scans rows (j<<3)|oct, j=0..23.
// Exact 16th-smallest threshold over 192 via truncated-merge chain.
template<int NT>
__device__ __forceinline__ float pass1_T8(const float (&xi)[H], float nd,
                                          const float* __restrict__ s_enc,
                                          const float* __restrict__ s_nrm,
                                          float* __restrict__ s_d,
                                          int oct, int t)
{
    float bd[16];
    #pragma unroll
    for (int k = 0; k < 16; k++) bd[k] = 1e30f;
    #pragma unroll 2
    for (int j = 0; j < 24; j++) {
        int row = (j << 3) | oct;
        float d = distf(xi, nd, s_enc + row * ROWP, s_nrm[row]);
        s_d[j * NT + t] = d;
        #pragma unroll
        for (int k = 0; k < 16; k++) {
            float lo = fminf(d, bd[k]);
            d = fmaxf(d, bd[k]);
            bd[k] = lo;
        }
    }
    float m[16];
    #pragma unroll
    for (int k = 0; k < 16; k++)
        m[k] = fminf(bd[k], __shfl_xor_sync(0xFFFFFFFFu, bd[15 - k], 1));
    bitonic16(m);
    #pragma unroll
    for (int k = 0; k < 16; k++)
        bd[k] = fminf(m[k], __shfl_xor_sync(0xFFFFFFFFu, m[15 - k], 2));
    bitonic16(bd);
    float T = -1e30f;
    #pragma unroll
    for (int k = 0; k < 16; k++)
        T = fmaxf(T, fminf(bd[k], __shfl_xor_sync(0xFFFFFFFFu, bd[15 - k], 4)));
    return T;
}

// pass2: compact selected via shared atomics, gather v split across the oct, reduce.
template<int NT>
__device__ __forceinline__ void select_maxv8(float T,
                                             const float* __restrict__ s_d,
                                             const float* __restrict__ s_v,
                                             int* __restrict__ s_cnt,
                                             int* __restrict__ s_sel,
                                             int dl, int oct, int t, float (&mv)[H])
{
    #pragma unroll 4
    for (int j = 0; j < 24; j++) {
        float d = s_d[j * NT + t];
        if (d <= T) {
            int p = atomicAdd(&s_cnt[dl], 1);
            if (p < 24) s_sel[dl * 24 + p] = (j << 3) | oct;
        }
    }
    __syncwarp();
    #pragma unroll
    for (int h = 0; h < H; h++) mv[h] = -1e30f;
    int n = s_cnt[dl]; if (n > 24) n = 24;
    for (int k = oct; k < n; k += 8) {
        int row = s_sel[dl * 24 + k];
        const float4* v4 = (const float4*)(s_v + row * ROWP);
        float4 q0 = v4[0], q1 = v4[1], q2 = v4[2], q3 = v4[3];
        mv[0]  = fmaxf(mv[0],  q0.x); mv[1]  = fmaxf(mv[1],  q0.y);
        mv[2]  = fmaxf(mv[2],  q0.z); mv[3]  = fmaxf(mv[3],  q0.w);
        mv[4]  = fmaxf(mv[4],  q1.x); mv[5]  = fmaxf(mv[5],  q1.y);
        mv[6]  = fmaxf(mv[6],  q1.z); mv[7]  = fmaxf(mv[7],  q1.w);
        mv[8]  = fmaxf(mv[8],  q2.x); mv[9]  = fmaxf(mv[9],  q2.y);
        mv[10] = fmaxf(mv[10], q2.z); mv[11] = fmaxf(mv[11], q2.w);
        mv[12] = fmaxf(mv[12], q3.x); mv[13] = fmaxf(mv[13], q3.y);
        mv[14] = fmaxf(mv[14], q3.z); mv[15] = fmaxf(mv[15], q3.w);
    }
    #pragma unroll
    for (int h = 0; h < H; h++) mv[h] = fmaxf(mv[h], __shfl_xor_sync(0xFFFFFFFFu, mv[h], 1));
    #pragma unroll
    for (int h = 0; h < H; h++) mv[h] = fmaxf(mv[h], __shfl_xor_sync(0xFFFFFFFFu, mv[h], 2));
    #pragma unroll
    for (int h = 0; h < H; h++) mv[h] = fmaxf(mv[h], __shfl_xor_sync(0xFFFFFFFFu, mv[h], 4));
}

// ==================== K0: encoders + u/v/nrm precompute ====================
__global__ void k_encode(const float* __restrict__ x_ts, const float* __restrict__ x_lc,
                         const float* __restrict__ tw1, const float* __restrict__ tb1,
                         const float* __restrict__ tw2, const float* __restrict__ tb2,
                         const float* __restrict__ lw1, const float* __restrict__ lb1,
                         const float* __restrict__ lw2, const float* __restrict__ lb2,
                         const float* __restrict__ cw,  const float* __restrict__ cb)
{
    int tid = blockIdx.x * blockDim.x + threadIdx.x;
    if (tid < NB) g_cnt[tid] = 0;   // reset pool tickets for kB
    if (tid < N_TS) {
        float x[6], h1[H], e[H];
        #pragma unroll
        for (int i = 0; i < 6; i++) x[i] = __ldg(&x_ts[tid * 6 + i]);
        #pragma unroll
        for (int o = 0; o < H; o++) {
            float s = __ldg(&tb1[o]);
            #pragma unroll
            for (int i = 0; i < 6; i++) s += x[i] * __ldg(&tw1[i * H + o]);
            h1[o] = eluf(s);
        }
        #pragma unroll
        for (int o = 0; o < H; o++) {
            float s = __ldg(&tb2[o]);
            #pragma unroll
            for (int i = 0; i < H; i++) s += h1[i] * __ldg(&tw2[i * H + o]);
            e[o] = eluf(s);
            g_ts_enc[tid * H + o] = e[o];
        }
        #pragma unroll
        for (int o = 0; o < H; o++) {
            float s = __ldg(&cb[o]);
            #pragma unroll
            for (int i = 0; i < H; i++)
                s += e[i] * (__ldg(&cw[i * H + o]) - __ldg(&cw[(H + i) * H + o]));
            g_u_ts[tid * H + o] = s;
        }
    } else if (tid < N_TS + N_LC) {
        int id = tid - N_TS;
        float x[5], h1[H], e[H];
        #pragma unroll
        for (int i = 0; i < 5; i++) x[i] = __ldg(&x_lc[id * 5 + i]);
        #pragma unroll
        for (int o = 0; o < H; o++) {
            float s = __ldg(&lb1[o]);
            #pragma unroll
            for (int i = 0; i < 5; i++) s += x[i] * __ldg(&lw1[i * H + o]);
            h1[o] = eluf(s);
        }
        #pragma unroll
        for (int o = 0; o < H; o++) {
            float s = __ldg(&lb2[o]);
            #pragma unroll
            for (int i = 0; i < H; i++) s += h1[i] * __ldg(&lw2[i * H + o]);
            e[o] = eluf(s);
            g_lc_enc[id * H + o] = e[o];
        }
        g_nrm_lc[id] = norm16(e);
        #pragma unroll
        for (int o = 0; o < H; o++) {
            float su = __ldg(&cb[o]), sv = 0.f;
            #pragma unroll
            for (int i = 0; i < H; i++) {
                float wt = __ldg(&cw[i * H + o]);
                float wb = __ldg(&cw[(H + i) * H + o]);
                su += e[i] * (wt - wb);
                sv += e[i] * wb;
            }
            g_u_lc[id * H + o] = su;
            g_v_lc[id * H + o] = sv;
        }
    }
}

// ================= kA: conv1 + conv2 (+u3/v3 fused), 32 dst x 8 thr =================
#define A_ENC 0
#define A_V   3840
#define A_NRM 7680
#define A_W   7872
#define A_B   8384
#define A_D   8400
#define A_F   14544
#define A_CNT 15184
#define A_SEL 15216
#define A_TOTF 15984   // 63936 bytes

__global__ void __launch_bounds__(256, 3)
kA(const float* __restrict__ cw, const float* __restrict__ cb)
{
    extern __shared__ float sm[];
    float* s_enc = sm + A_ENC;
    float* s_v   = sm + A_V;
    float* s_nrm = sm + A_NRM;
    float* s_w   = sm + A_W;
    float* s_b   = sm + A_B;
    float* s_d   = sm + A_D;
    float* s_f   = sm + A_F;
    int*   s_cnt = (int*)(sm + A_CNT);
    int*   s_sel = (int*)(sm + A_SEL);

    const int g = blockIdx.x / 10, part = blockIdx.x % 10;
    const int t = threadIdx.x;
    const bool isLC = part < 6;

    // ---- stage src (lc_enc, v_lc, nrm) + weights ----
    {
        const float4* ge = (const float4*)(g_lc_enc + g * LCB * H);
        const float4* gv = (const float4*)(g_v_lc  + g * LCB * H);
        float4* se = (float4*)s_enc; float4* sv = (float4*)s_v;
        #pragma unroll
        for (int i = t; i < LCB * 4; i += 256) {
            int r = i >> 2, c = i & 3;
            se[r * 5 + c] = __ldg(&ge[i]);
            sv[r * 5 + c] = __ldg(&gv[i]);
        }
        if (t < LCB) s_nrm[t] = __ldg(&g_nrm_lc[g * LCB + t]);
        for (int i = t; i < 512; i += 256) s_w[i] = __ldg(&cw[i]);
        if (t < 16) s_b[t] = __ldg(&cb[t]);
        if (t < 32) s_cnt[t] = 0;
    }
    __syncthreads();

    const int dl = t >> 3, oct = t & 7;
    const int dstRow = isLC ? g * LCB + part * 32 + dl
                            : g * TSB + (part - 6) * 32 + dl;
    float xi[H];
    if (isLC) ld16s(xi, s_enc + (part * 32 + dl) * ROWP);
    else      ld16g(xi, g_ts_enc + dstRow * H);
    float nd = norm16(xi);

    float T = pass1_T8<256>(xi, nd, s_enc, s_nrm, s_d, oct, t);
    float mv[H];
    select_maxv8<256>(T, s_d, s_v, s_cnt, s_sel, dl, oct, t, mv);

    // epilogue: each lane computes its 2 channels, exchanges for full f
    const int ch0 = oct * 2;
    const float* uPtr = (isLC ? g_u_lc : g_u_ts) + dstRow * H;
    float u0 = __ldg(&uPtr[ch0]), u1 = __ldg(&uPtr[ch0 + 1]);
    float fa = eluf(u0 + mv[ch0]), fb = eluf(u1 + mv[ch0 + 1]);
    s_f[dl * ROWP + ch0] = fa; s_f[dl * ROWP + ch0 + 1] = fb;
    __syncwarp();
    float f[H];
    ld16s(f, s_f + dl * ROWP);

    if (isLC) {
        *(float2*)&g_f1[dstRow * H + ch0] = make_float2(fa, fb);
        float a0 = 0.f, a1 = 0.f;
        #pragma unroll
        for (int i = 0; i < H; i++) {
            a0 = fmaf(f[i], s_w[(H + i) * H + ch0], a0);
            a1 = fmaf(f[i], s_w[(H + i) * H + ch0 + 1], a1);
        }
        *(float2*)&g_v3[dstRow * H + ch0] = make_float2(a0, a1);
        if (oct == 0) g_nrm3[dstRow] = norm16(f);
    } else {
        *(float2*)&g_f2[dstRow * H + ch0] = make_float2(fa, fb);
        float a0 = s_b[ch0], a1 = s_b[ch0 + 1];
        #pragma unroll
        for (int i = 0; i < H; i++) {
            a0 = fmaf(f[i], s_w[i * H + ch0] - s_w[(H + i) * H + ch0], a0);
            a1 = fmaf(f[i], s_w[i * H + ch0 + 1] - s_w[(H + i) * H + ch0 + 1], a1);
        }
        *(float2*)&g_u3[dstRow * H + ch0] = make_float2(a0, a1);
    }
}

// ================= kB: conv3 + pool + head, 16 dst x 8 thr =================
#define B_ENC  0
#define B_V    3840
#define B_NRM  7680
#define B_D    7872
#define B_POOL 10944
#define B_PLD  11264
#define B_H1   11280
#define B_H2   11344
#define B_H3   11376
#define B_H4   11384
#define B_CNT  11388
#define B_SEL  11404
#define B_FLAG 11788
#define B_TOTF 11792   // 47168 bytes

__global__ void __launch_bounds__(128, 4)
kB(const float* __restrict__ w1, const float* __restrict__ b1,
   const float* __restrict__ w2, const float* __restrict__ b2,
   const float* __restrict__ w3, const float* __restrict__ b3,
   const float* __restrict__ w4, const float* __restrict__ b4,
   const float* __restrict__ w5, const float* __restrict__ b5,
   float* __restrict__ out, int out_size)
{
    extern __shared__ float sm[];
    float* s_enc  = sm + B_ENC;
    float* s_v    = sm + B_V;
    float* s_nrm  = sm + B_NRM;
    float* s_d    = sm + B_D;
    float* s_pool = sm + B_POOL;
    float* pooled = sm + B_PLD;
    float* h1s    = sm + B_H1;
    float* h2s    = sm + B_H2;
    float* h3s    = sm + B_H3;
    float* h4s    = sm + B_H4;
    int*   s_cnt  = (int*)(sm + B_CNT);
    int*   s_sel  = (int*)(sm + B_SEL);
    int*   s_flag = (int*)(sm + B_FLAG);

    const int g = blockIdx.x >> 3, qpart = blockIdx.x & 7;
    const int t = threadIdx.x;

    {
        const float4* ge = (const float4*)(g_f1 + g * LCB * H);
        const float4* gv = (const float4*)(g_v3 + g * LCB * H);
        float4* se = (float4*)s_enc; float4* sv = (float4*)s_v;
        #pragma unroll
        for (int i = t; i < LCB * 4; i += 128) {
            int r = i >> 2, c = i & 3;
            se[r * 5 + c] = __ldg(&ge[i]);
            sv[r * 5 + c] = __ldg(&gv[i]);
        }
        for (int i = t; i < LCB; i += 128) s_nrm[i] = __ldg(&g_nrm3[g * LCB + i]);
        if (t < 16) s_cnt[t] = 0;
    }
    __syncthreads();

    const int dl = t >> 3, oct = t & 7;
    const int dstRow = g * TSB + qpart * 16 + dl;
    float xi[H];
    ld16g(xi, g_f2 + dstRow * H);
    float nd = norm16(xi);

    float T = pass1_T8<128>(xi, nd, s_enc, s_nrm, s_d, oct, t);
    float mv[H];
    select_maxv8<128>(T, s_d, s_v, s_cnt, s_sel, dl, oct, t, mv);

    const int ch0 = oct * 2;
    float u0 = __ldg(&g_u3[dstRow * H + ch0]), u1 = __ldg(&g_u3[dstRow * H + ch0 + 1]);
    s_pool[dl * ROWP + ch0]     = eluf(u0 + mv[ch0]);
    s_pool[dl * ROWP + ch0 + 1] = eluf(u1 + mv[ch0 + 1]);
    __syncthreads();

    if (t < H) {
        float a = 0.f;
        #pragma unroll
        for (int d = 0; d < 16; d++) a += s_pool[d * ROWP + t];
        g_part[(g * 8 + qpart) * H + t] = a;
    }
    __threadfence();
    __syncthreads();
    if (t == 0) {
        int tk = atomicAdd(&g_cnt[g], 1);
        s_flag[0] = (tk == 7);
    }
    __syncthreads();

    if (s_flag[0]) {
        __threadfence();
        if (t < H) {
            const float* pp = g_part + g * 8 * H + t;
            float p01 = pp[0] + pp[H];
            float p23 = pp[2*H] + pp[3*H];
            float p45 = pp[4*H] + pp[5*H];
            float p67 = pp[6*H] + pp[7*H];
            pooled[t] = ((p01 + p23) + (p45 + p67)) * (1.f / (float)TSB);
        }
        __syncthreads();
        if (t < 64) {
            float sv = __ldg(&b1[t]);
            #pragma unroll
            for (int i = 0; i < H; i++) sv += pooled[i] * __ldg(&w1[i * 64 + t]);
            h1s[t] = eluf(sv);
        }
        __syncthreads();
        if (t < 32) {
            float sv = __ldg(&b2[t]);
            #pragma unroll
            for (int i = 0; i < 64; i++) sv += h1s[i] * __ldg(&w2[i * 32 + t]);
            h2s[t] = eluf(sv);
        }
        __syncthreads();
        if (t < 8) {
            float sv = __ldg(&b3[t]);
            #pragma unroll
            for (int i = 0; i < 32; i++) sv += h2s[i] * __ldg(&w3[i * 8 + t]);
            h3s[t] = eluf(sv);
        }
        __syncthreads();
        if (t < 4) {
            float sv = __ldg(&b4[t]);
            #pragma unroll
            for (int i = 0; i < 8; i++) sv += h3s[i] * __ldg(&w4[i * 4 + t]);
            h4s[t] = eluf(sv);
        }
        __syncthreads();
        if (t == 0) {
            float sv = __ldg(&b5[0]);
            #pragma unroll
            for (int i = 0; i < 4; i++) sv += h4s[i] * __ldg(&w5[i]);
            if (g < out_size) out[g] = sv;
            if (NB + g < out_size) out[NB + g] = (float)g;
        }
    }
}

// ==================== launch ====================
extern "C" void kernel_launch(void* const* d_in, const int* in_sizes, int n_in,
                              void* d_out, int out_size)
{
    const float* x_ts = (const float*)d_in[0];
    const float* x_lc = (const float*)d_in[1];
    const float* tw1 = (const float*)d_in[4];
    const float* tb1 = (const float*)d_in[5];
    const float* tw2 = (const float*)d_in[6];
    const float* tb2 = (const float*)d_in[7];
    const float* lw1 = (const float*)d_in[8];
    const float* lb1 = (const float*)d_in[9];
    const float* lw2 = (const float*)d_in[10];
    const float* lb2 = (const float*)d_in[11];
    const float* cw  = (const float*)d_in[12];
    const float* cb  = (const float*)d_in[13];
    const float* w1  = (const float*)d_in[14];
    const float* b1  = (const float*)d_in[15];
    const float* w2  = (const float*)d_in[16];
    const float* b2  = (const float*)d_in[17];
    const float* w3  = (const float*)d_in[18];
    const float* b3  = (const float*)d_in[19];
    const float* w4  = (const float*)d_in[20];
    const float* b4  = (const float*)d_in[21];
    const float* w5  = (const float*)d_in[22];
    const float* b5  = (const float*)d_in[23];

    cudaFuncSetAttribute(kA, cudaFuncAttributeMaxDynamicSharedMemorySize, A_TOTF * 4);
    cudaFuncSetAttribute(kB, cudaFuncAttributeMaxDynamicSharedMemorySize, B_TOTF * 4);

    k_encode<<<(N_TS + N_LC) / 128, 128>>>(x_ts, x_lc, tw1, tb1, tw2, tb2,
                                           lw1, lb1, lw2, lb2, cw, cb);
    kA<<<NB * 10, 256, A_TOTF * 4>>>(cw, cb);
    kB<<<NB * 8, 128, B_TOTF * 4>>>(w1, b1, w2, b2, w3, b3, w4, b4, w5, b5,
                                    (float*)d_out, out_size);
}

// round 8
// speedup vs baseline: 2.1542x; 1.0396x over previous
#include <cuda_runtime.h>
#include <math.h>

#define N_TS 8192
#define N_LC 12288
#define NB   64
#define TSB  128
#define LCB  192
#define H    16
#define ROWP 20

// ---------------- global scratch ----------------
__device__ float g_ts_enc[N_TS * H];
__device__ float g_u_ts [N_TS * H];
__device__ float g_lc_enc[N_LC * H];
__device__ float g_u_lc [N_LC * H];
__device__ float g_v_lc [N_LC * H];
__device__ float g_nrm_lc[N_LC];
__device__ float g_f1  [N_LC * H];
__device__ float g_v3  [N_LC * H];
__device__ float g_nrm3[N_LC];
__device__ float g_f2  [N_TS * H];
__device__ float g_u3  [N_TS * H];
__device__ float g_part[NB * 8 * H];
__device__ int   g_cnt [NB];

__device__ __forceinline__ float eluf(float x) { return x > 0.f ? x : expm1f(x); }

__device__ __forceinline__ void ld16s(float (&x)[H], const float* p) {
    const float4* p4 = (const float4*)p;
    #pragma unroll
    for (int q = 0; q < 4; q++) {
        float4 v = p4[q];
        x[4*q] = v.x; x[4*q+1] = v.y; x[4*q+2] = v.z; x[4*q+3] = v.w;
    }
}
__device__ __forceinline__ void ld16g(float (&x)[H], const float* p) {
    const float4* p4 = (const float4*)p;
    #pragma unroll
    for (int q = 0; q < 4; q++) {
        float4 v = __ldg(&p4[q]);
        x[4*q] = v.x; x[4*q+1] = v.y; x[4*q+2] = v.z; x[4*q+3] = v.w;
    }
}

__device__ __forceinline__ float distf(const float (&xi)[H], float nd,
                                       const float* __restrict__ sp, float nj)
{
    const float4* p4 = (const float4*)sp;
    float4 p0 = p4[0], p1 = p4[1], p2 = p4[2], p3 = p4[3];
    float d0 = fmaf(xi[0],  p0.x, fmaf(xi[1],  p0.y, fmaf(xi[2],  p0.z, xi[3]  * p0.w)));
    float d1 = fmaf(xi[4],  p1.x, fmaf(xi[5],  p1.y, fmaf(xi[6],  p1.z, xi[7]  * p1.w)));
    float d2 = fmaf(xi[8],  p2.x, fmaf(xi[9],  p2.y, fmaf(xi[10], p2.z, xi[11] * p2.w)));
    float d3 = fmaf(xi[12], p3.x, fmaf(xi[13], p3.y, fmaf(xi[14], p3.z, xi[15] * p3.w)));
    float dot = __fadd_rn(__fadd_rn(d0, d1), __fadd_rn(d2, d3));
    return fmaf(-2.0f, dot, __fadd_rn(nd, nj));
}

__device__ __forceinline__ float norm16(const float (&x)[H]) {
    float n0 = fmaf(x[0],  x[0],  fmaf(x[1],  x[1],  fmaf(x[2],  x[2],  x[3]  * x[3])));
    float n1 = fmaf(x[4],  x[4],  fmaf(x[5],  x[5],  fmaf(x[6],  x[6],  x[7]  * x[7])));
    float n2 = fmaf(x[8],  x[8],  fmaf(x[9],  x[9],  fmaf(x[10], x[10], x[11] * x[11])));
    float n3 = fmaf(x[12], x[12], fmaf(x[13], x[13], fmaf(x[14], x[14], x[15] * x[15])));
    return (n0 + n1) + (n2 + n3);
}

__device__ __forceinline__ void bitonic16(float (&m)[16]) {
    #pragma unroll
    for (int j = 8; j > 0; j >>= 1) {
        #pragma unroll
        for (int i = 0; i < 16; i++) {
            if ((i & j) == 0) {
                float lo = fminf(m[i], m[i + j]);
                m[i + j] = fmaxf(m[i], m[i + j]);
                m[i] = lo;
            }
        }
    }
}

template<int NT>
__device__ __forceinline__ float pass1_T8(const float (&xi)[H], float nd,
                                          const float* __restrict__ s_enc,
                                          const float* __restrict__ s_nrm,
                                          float* __restrict__ s_d,
                                          int oct, int t)
{
    float bd[16];
    #pragma unroll
    for (int k = 0; k < 16; k++) bd[k] = 1e30f;
    #pragma unroll 2
    for (int j = 0; j < 24; j++) {
        int row = (j << 3) | oct;
        float d = distf(xi, nd, s_enc + row * ROWP, s_nrm[row]);
        s_d[j * NT + t] = d;
        #pragma unroll
        for (int k = 0; k < 16; k++) {
            float lo = fminf(d, bd[k]);
            d = fmaxf(d, bd[k]);
            bd[k] = lo;
        }
    }
    float m[16];
    #pragma unroll
    for (int k = 0; k < 16; k++)
        m[k] = fminf(bd[k], __shfl_xor_sync(0xFFFFFFFFu, bd[15 - k], 1));
    bitonic16(m);
    #pragma unroll
    for (int k = 0; k < 16; k++)
        bd[k] = fminf(m[k], __shfl_xor_sync(0xFFFFFFFFu, m[15 - k], 2));
    bitonic16(bd);
    float T = -1e30f;
    #pragma unroll
    for (int k = 0; k < 16; k++)
        T = fmaxf(T, fminf(bd[k], __shfl_xor_sync(0xFFFFFFFFu, bd[15 - k], 4)));
    return T;
}

template<int NT>
__device__ __forceinline__ void select_maxv8(float T,
                                             const float* __restrict__ s_d,
                                             const float* __restrict__ s_v,
                                             int* __restrict__ s_cnt,
                                             int* __restrict__ s_sel,
                                             int dl, int oct, int t, float (&mv)[H])
{
    #pragma unroll 4
    for (int j = 0; j < 24; j++) {
        float d = s_d[j * NT + t];
        if (d <= T) {
            int p = atomicAdd(&s_cnt[dl], 1);
            if (p < 24) s_sel[dl * 24 + p] = (j << 3) | oct;
        }
    }
    __syncwarp();
    #pragma unroll
    for (int h = 0; h < H; h++) mv[h] = -1e30f;
    int n = s_cnt[dl]; if (n > 24) n = 24;
    for (int k = oct; k < n; k += 8) {
        int row = s_sel[dl * 24 + k];
        const float4* v4 = (const float4*)(s_v + row * ROWP);
        float4 q0 = v4[0], q1 = v4[1], q2 = v4[2], q3 = v4[3];
        mv[0]  = fmaxf(mv[0],  q0.x); mv[1]  = fmaxf(mv[1],  q0.y);
        mv[2]  = fmaxf(mv[2],  q0.z); mv[3]  = fmaxf(mv[3],  q0.w);
        mv[4]  = fmaxf(mv[4],  q1.x); mv[5]  = fmaxf(mv[5],  q1.y);
        mv[6]  = fmaxf(mv[6],  q1.z); mv[7]  = fmaxf(mv[7],  q1.w);
        mv[8]  = fmaxf(mv[8],  q2.x); mv[9]  = fmaxf(mv[9],  q2.y);
        mv[10] = fmaxf(mv[10], q2.z); mv[11] = fmaxf(mv[11], q2.w);
        mv[12] = fmaxf(mv[12], q3.x); mv[13] = fmaxf(mv[13], q3.y);
        mv[14] = fmaxf(mv[14], q3.z); mv[15] = fmaxf(mv[15], q3.w);
    }
    #pragma unroll
    for (int h = 0; h < H; h++) mv[h] = fmaxf(mv[h], __shfl_xor_sync(0xFFFFFFFFu, mv[h], 1));
    #pragma unroll
    for (int h = 0; h < H; h++) mv[h] = fmaxf(mv[h], __shfl_xor_sync(0xFFFFFFFFu, mv[h], 2));
    #pragma unroll
    for (int h = 0; h < H; h++) mv[h] = fmaxf(mv[h], __shfl_xor_sync(0xFFFFFFFFu, mv[h], 4));
}

// ==================== K0: encoders (smem weights, float4 LDS) ====================
// smem weight layout (floats):
//   0: tw1(96) | 96: tb1(16) | 112: tw2(256) | 368: tb2(16)
// 384: lw1(80) | 464: lb1(16)| 480: lw2(256) | 736: lb2(16)
// 752: cw(512) | 1264: cb(16)   total 1280 floats
__global__ void __launch_bounds__(128)
k_encode(const float* __restrict__ x_ts, const float* __restrict__ x_lc,
         const float* __restrict__ tw1, const float* __restrict__ tb1,
         const float* __restrict__ tw2, const float* __restrict__ tb2,
         const float* __restrict__ lw1, const float* __restrict__ lb1,
         const float* __restrict__ lw2, const float* __restrict__ lb2,
         const float* __restrict__ cw,  const float* __restrict__ cb)
{
    __shared__ float s_ew[1280];
    const int t = threadIdx.x;
    for (int i = t; i < 1280; i += 128) {
        float val;
        if      (i < 96)   val = __ldg(&tw1[i]);
        else if (i < 112)  val = __ldg(&tb1[i - 96]);
        else if (i < 368)  val = __ldg(&tw2[i - 112]);
        else if (i < 384)  val = __ldg(&tb2[i - 368]);
        else if (i < 464)  val = __ldg(&lw1[i - 384]);
        else if (i < 480)  val = __ldg(&lb1[i - 464]);
        else if (i < 736)  val = __ldg(&lw2[i - 480]);
        else if (i < 752)  val = __ldg(&lb2[i - 736]);
        else if (i < 1264) val = __ldg(&cw[i - 752]);
        else               val = __ldg(&cb[i - 1264]);
        s_ew[i] = val;
    }
    __syncthreads();

    const int tid = blockIdx.x * 128 + t;
    if (tid < NB) g_cnt[tid] = 0;   // reset pool tickets for kB

    if (tid < N_TS) {
        // ---- TS point ----
        float x[6], h1[H], e[H], acc[H];
        #pragma unroll
        for (int i = 0; i < 6; i++) x[i] = __ldg(&x_ts[tid * 6 + i]);
        #pragma unroll
        for (int o = 0; o < H; o++) acc[o] = s_ew[96 + o];
        #pragma unroll
        for (int i = 0; i < 6; i++) {
            const float4* r = (const float4*)&s_ew[i * H];
            float4 a = r[0], b = r[1], c = r[2], d = r[3];
            float xi = x[i];
            acc[0]+=xi*a.x; acc[1]+=xi*a.y; acc[2]+=xi*a.z; acc[3]+=xi*a.w;
            acc[4]+=xi*b.x; acc[5]+=xi*b.y; acc[6]+=xi*b.z; acc[7]+=xi*b.w;
            acc[8]+=xi*c.x; acc[9]+=xi*c.y; acc[10]+=xi*c.z; acc[11]+=xi*c.w;
            acc[12]+=xi*d.x; acc[13]+=xi*d.y; acc[14]+=xi*d.z; acc[15]+=xi*d.w;
        }
        #pragma unroll
        for (int o = 0; o < H; o++) h1[o] = eluf(acc[o]);

        #pragma unroll
        for (int o = 0; o < H; o++) acc[o] = s_ew[368 + o];
        #pragma unroll
        for (int i = 0; i < H; i++) {
            const float4* r = (const float4*)&s_ew[112 + i * H];
            float4 a = r[0], b = r[1], c = r[2], d = r[3];
            float xi = h1[i];
            acc[0]+=xi*a.x; acc[1]+=xi*a.y; acc[2]+=xi*a.z; acc[3]+=xi*a.w;
            acc[4]+=xi*b.x; acc[5]+=xi*b.y; acc[6]+=xi*b.z; acc[7]+=xi*b.w;
            acc[8]+=xi*c.x; acc[9]+=xi*c.y; acc[10]+=xi*c.z; acc[11]+=xi*c.w;
            acc[12]+=xi*d.x; acc[13]+=xi*d.y; acc[14]+=xi*d.z; acc[15]+=xi*d.w;
        }
        #pragma unroll
        for (int o = 0; o < H; o++) e[o] = eluf(acc[o]);
        float4* ge = (float4*)&g_ts_enc[tid * H];
        #pragma unroll
        for (int q = 0; q < 4; q++)
            ge[q] = make_float4(e[4*q], e[4*q+1], e[4*q+2], e[4*q+3]);

        // u = cb + e @ (Wt - Wb)
        #pragma unroll
        for (int o = 0; o < H; o++) acc[o] = s_ew[1264 + o];
        #pragma unroll
        for (int i = 0; i < H; i++) {
            const float4* rt = (const float4*)&s_ew[752 + i * H];
            const float4* rb = (const float4*)&s_ew[752 + (H + i) * H];
            float4 a = rt[0], b = rt[1], c = rt[2], d = rt[3];
            float4 a2 = rb[0], b2 = rb[1], c2 = rb[2], d2 = rb[3];
            float xi = e[i];
            acc[0]+=xi*(a.x-a2.x); acc[1]+=xi*(a.y-a2.y); acc[2]+=xi*(a.z-a2.z); acc[3]+=xi*(a.w-a2.w);
            acc[4]+=xi*(b.x-b2.x); acc[5]+=xi*(b.y-b2.y); acc[6]+=xi*(b.z-b2.z); acc[7]+=xi*(b.w-b2.w);
            acc[8]+=xi*(c.x-c2.x); acc[9]+=xi*(c.y-c2.y); acc[10]+=xi*(c.z-c2.z); acc[11]+=xi*(c.w-c2.w);
            acc[12]+=xi*(d.x-d2.x); acc[13]+=xi*(d.y-d2.y); acc[14]+=xi*(d.z-d2.z); acc[15]+=xi*(d.w-d2.w);
        }
        float4* gu = (float4*)&g_u_ts[tid * H];
        #pragma unroll
        for (int q = 0; q < 4; q++)
            gu[q] = make_float4(acc[4*q], acc[4*q+1], acc[4*q+2], acc[4*q+3]);
    } else if (tid < N_TS + N_LC) {
        // ---- LC point ----
        int id = tid - N_TS;
        float x[5], h1[H], e[H], acc[H], accv[H];
        #pragma unroll
        for (int i = 0; i < 5; i++) x[i] = __ldg(&x_lc[id * 5 + i]);
        #pragma unroll
        for (int o = 0; o < H; o++) acc[o] = s_ew[464 + o];
        #pragma unroll
        for (int i = 0; i < 5; i++) {
            const float4* r = (const float4*)&s_ew[384 + i * H];
            float4 a = r[0], b = r[1], c = r[2], d = r[3];
            float xi = x[i];
            acc[0]+=xi*a.x; acc[1]+=xi*a.y; acc[2]+=xi*a.z; acc[3]+=xi*a.w;
            acc[4]+=xi*b.x; acc[5]+=xi*b.y; acc[6]+=xi*b.z; acc[7]+=xi*b.w;
            acc[8]+=xi*c.x; acc[9]+=xi*c.y; acc[10]+=xi*c.z; acc[11]+=xi*c.w;
            acc[12]+=xi*d.x; acc[13]+=xi*d.y; acc[14]+=xi*d.z; acc[15]+=xi*d.w;
        }
        #pragma unroll
        for (int o = 0; o < H; o++) h1[o] = eluf(acc[o]);

        #pragma unroll
        for (int o = 0; o < H; o++) acc[o] = s_ew[736 + o];
        #pragma unroll
        for (int i = 0; i < H; i++) {
            const float4* r = (const float4*)&s_ew[480 + i * H];
            float4 a = r[0], b = r[1], c = r[2], d = r[3];
            float xi = h1[i];
            acc[0]+=xi*a.x; acc[1]+=xi*a.y; acc[2]+=xi*a.z; acc[3]+=xi*a.w;
            acc[4]+=xi*b.x; acc[5]+=xi*b.y; acc[6]+=xi*b.z; acc[7]+=xi*b.w;
            acc[8]+=xi*c.x; acc[9]+=xi*c.y; acc[10]+=xi*c.z; acc[11]+=xi*c.w;
            acc[12]+=xi*d.x; acc[13]+=xi*d.y; acc[14]+=xi*d.z; acc[15]+=xi*d.w;
        }
        #pragma unroll
        for (int o = 0; o < H; o++) e[o] = eluf(acc[o]);
        float4* ge = (float4*)&g_lc_enc[id * H];
        #pragma unroll
        for (int q = 0; q < 4; q++)
            ge[q] = make_float4(e[4*q], e[4*q+1], e[4*q+2], e[4*q+3]);
        g_nrm_lc[id] = norm16(e);

        // u = cb + e@(Wt-Wb);  v = e@Wb
        #pragma unroll
        for (int o = 0; o < H; o++) { acc[o] = s_ew[1264 + o]; accv[o] = 0.f; }
        #pragma unroll
        for (int i = 0; i < H; i++) {
            const float4* rt = (const float4*)&s_ew[752 + i * H];
            const float4* rb = (const float4*)&s_ew[752 + (H + i) * H];
            float4 a = rt[0], b = rt[1], c = rt[2], d = rt[3];
            float4 a2 = rb[0], b2 = rb[1], c2 = rb[2], d2 = rb[3];
            float xi = e[i];
            acc[0]+=xi*(a.x-a2.x); acc[1]+=xi*(a.y-a2.y); acc[2]+=xi*(a.z-a2.z); acc[3]+=xi*(a.w-a2.w);
            acc[4]+=xi*(b.x-b2.x); acc[5]+=xi*(b.y-b2.y); acc[6]+=xi*(b.z-b2.z); acc[7]+=xi*(b.w-b2.w);
            acc[8]+=xi*(c.x-c2.x); acc[9]+=xi*(c.y-c2.y); acc[10]+=xi*(c.z-c2.z); acc[11]+=xi*(c.w-c2.w);
            acc[12]+=xi*(d.x-d2.x); acc[13]+=xi*(d.y-d2.y); acc[14]+=xi*(d.z-d2.z); acc[15]+=xi*(d.w-d2.w);
            accv[0]+=xi*a2.x; accv[1]+=xi*a2.y; accv[2]+=xi*a2.z; accv[3]+=xi*a2.w;
            accv[4]+=xi*b2.x; accv[5]+=xi*b2.y; accv[6]+=xi*b2.z; accv[7]+=xi*b2.w;
            accv[8]+=xi*c2.x; accv[9]+=xi*c2.y; accv[10]+=xi*c2.z; accv[11]+=xi*c2.w;
            accv[12]+=xi*d2.x; accv[13]+=xi*d2.y; accv[14]+=xi*d2.z; accv[15]+=xi*d2.w;
        }
        float4* gu = (float4*)&g_u_lc[id * H];
        float4* gv = (float4*)&g_v_lc[id * H];
        #pragma unroll
        for (int q = 0; q < 4; q++) {
            gu[q] = make_float4(acc[4*q], acc[4*q+1], acc[4*q+2], acc[4*q+3]);
            gv[q] = make_float4(accv[4*q], accv[4*q+1], accv[4*q+2], accv[4*q+3]);
        }
    }
}

// ================= kA: conv1 + conv2 (+u3/v3 fused), 32 dst x 8 thr =================
#define A_ENC 0
#define A_V   3840
#define A_NRM 7680
#define A_W   7872
#define A_B   8384
#define A_D   8400
#define A_F   14544
#define A_CNT 15184
#define A_SEL 15216
#define A_TOTF 15984   // 63936 bytes

__global__ void __launch_bounds__(256, 3)
kA(const float* __restrict__ cw, const float* __restrict__ cb)
{
    extern __shared__ float sm[];
    float* s_enc = sm + A_ENC;
    float* s_v   = sm + A_V;
    float* s_nrm = sm + A_NRM;
    float* s_w   = sm + A_W;
    float* s_b   = sm + A_B;
    float* s_d   = sm + A_D;
    float* s_f   = sm + A_F;
    int*   s_cnt = (int*)(sm + A_CNT);
    int*   s_sel = (int*)(sm + A_SEL);

    const int g = blockIdx.x / 10, part = blockIdx.x % 10;
    const int t = threadIdx.x;
    const bool isLC = part < 6;

    {
        const float4* ge = (const float4*)(g_lc_enc + g * LCB * H);
        const float4* gv = (const float4*)(g_v_lc  + g * LCB * H);
        float4* se = (float4*)s_enc; float4* sv = (float4*)s_v;
        #pragma unroll
        for (int i = t; i < LCB * 4; i += 256) {
            int r = i >> 2, c = i & 3;
            se[r * 5 + c] = __ldg(&ge[i]);
            sv[r * 5 + c] = __ldg(&gv[i]);
        }
        if (t < LCB) s_nrm[t] = __ldg(&g_nrm_lc[g * LCB + t]);
        for (int i = t; i < 512; i += 256) s_w[i] = __ldg(&cw[i]);
        if (t < 16) s_b[t] = __ldg(&cb[t]);
        if (t < 32) s_cnt[t] = 0;
    }
    __syncthreads();

    const int dl = t >> 3, oct = t & 7;
    const int dstRow = isLC ? g * LCB + part * 32 + dl
                            : g * TSB + (part - 6) * 32 + dl;
    float xi[H];
    if (isLC) ld16s(xi, s_enc + (part * 32 + dl) * ROWP);
    else      ld16g(xi, g_ts_enc + dstRow * H);
    float nd = norm16(xi);

    float T = pass1_T8<256>(xi, nd, s_enc, s_nrm, s_d, oct, t);
    float mv[H];
    select_maxv8<256>(T, s_d, s_v, s_cnt, s_sel, dl, oct, t, mv);

    const int ch0 = oct * 2;
    const float* uPtr = (isLC ? g_u_lc : g_u_ts) + dstRow * H;
    float u0 = __ldg(&uPtr[ch0]), u1 = __ldg(&uPtr[ch0 + 1]);
    float fa = eluf(u0 + mv[ch0]), fb = eluf(u1 + mv[ch0 + 1]);
    s_f[dl * ROWP + ch0] = fa; s_f[dl * ROWP + ch0 + 1] = fb;
    __syncwarp();
    float f[H];
    ld16s(f, s_f + dl * ROWP);

    if (isLC) {
        *(float2*)&g_f1[dstRow * H + ch0] = make_float2(fa, fb);
        float a0 = 0.f, a1 = 0.f;
        #pragma unroll
        for (int i = 0; i < H; i++) {
            a0 = fmaf(f[i], s_w[(H + i) * H + ch0], a0);
            a1 = fmaf(f[i], s_w[(H + i) * H + ch0 + 1], a1);
        }
        *(float2*)&g_v3[dstRow * H + ch0] = make_float2(a0, a1);
        if (oct == 0) g_nrm3[dstRow] = norm16(f);
    } else {
        *(float2*)&g_f2[dstRow * H + ch0] = make_float2(fa, fb);
        float a0 = s_b[ch0], a1 = s_b[ch0 + 1];
        #pragma unroll
        for (int i = 0; i < H; i++) {
            a0 = fmaf(f[i], s_w[i * H + ch0] - s_w[(H + i) * H + ch0], a0);
            a1 = fmaf(f[i], s_w[i * H + ch0 + 1] - s_w[(H + i) * H + ch0 + 1], a1);
        }
        *(float2*)&g_u3[dstRow * H + ch0] = make_float2(a0, a1);
    }
}

// ================= kB: conv3 + pool + head, 16 dst x 8 thr =================
#define B_ENC  0
#define B_V    3840
#define B_NRM  7680
#define B_D    7872
#define B_POOL 10944
#define B_PLD  11264
#define B_H1   11280
#define B_H2   11344
#define B_H3   11376
#define B_H4   11384
#define B_CNT  11388
#define B_SEL  11404
#define B_FLAG 11788
#define B_TOTF 11792   // 47168 bytes

__global__ void __launch_bounds__(128, 4)
kB(const float* __restrict__ w1, const float* __restrict__ b1,
   const float* __restrict__ w2, const float* __restrict__ b2,
   const float* __restrict__ w3, const float* __restrict__ b3,
   const float* __restrict__ w4, const float* __restrict__ b4,
   const float* __restrict__ w5, const float* __restrict__ b5,
   float* __restrict__ out, int out_size)
{
    extern __shared__ float sm[];
    float* s_enc  = sm + B_ENC;
    float* s_v    = sm + B_V;
    float* s_nrm  = sm + B_NRM;
    float* s_d    = sm + B_D;
    float* s_pool = sm + B_POOL;
    float* pooled = sm + B_PLD;
    float* h1s    = sm + B_H1;
    float* h2s    = sm + B_H2;
    float* h3s    = sm + B_H3;
    float* h4s    = sm + B_H4;
    int*   s_cnt  = (int*)(sm + B_CNT);
    int*   s_sel  = (int*)(sm + B_SEL);
    int*   s_flag = (int*)(sm + B_FLAG);

    const int g = blockIdx.x >> 3, qpart = blockIdx.x & 7;
    const int t = threadIdx.x;

    {
        const float4* ge = (const float4*)(g_f1 + g * LCB * H);
        const float4* gv = (const float4*)(g_v3 + g * LCB * H);
        float4* se = (float4*)s_enc; float4* sv = (float4*)s_v;
        #pragma unroll
        for (int i = t; i < LCB * 4; i += 128) {
            int r = i >> 2, c = i & 3;
            se[r * 5 + c] = __ldg(&ge[i]);
            sv[r * 5 + c] = __ldg(&gv[i]);
        }
        for (int i = t; i < LCB; i += 128) s_nrm[i] = __ldg(&g_nrm3[g * LCB + i]);
        if (t < 16) s_cnt[t] = 0;
    }
    __syncthreads();

    const int dl = t >> 3, oct = t & 7;
    const int dstRow = g * TSB + qpart * 16 + dl;
    float xi[H];
    ld16g(xi, g_f2 + dstRow * H);
    float nd = norm16(xi);

    float T = pass1_T8<128>(xi, nd, s_enc, s_nrm, s_d, oct, t);
    float mv[H];
    select_maxv8<128>(T, s_d, s_v, s_cnt, s_sel, dl, oct, t, mv);

    const int ch0 = oct * 2;
    float u0 = __ldg(&g_u3[dstRow * H + ch0]), u1 = __ldg(&g_u3[dstRow * H + ch0 + 1]);
    s_pool[dl * ROWP + ch0]     = eluf(u0 + mv[ch0]);
    s_pool[dl * ROWP + ch0 + 1] = eluf(u1 + mv[ch0 + 1]);
    __syncthreads();

    if (t < H) {
        float a = 0.f;
        #pragma unroll
        for (int d = 0; d < 16; d++) a += s_pool[d * ROWP + t];
        g_part[(g * 8 + qpart) * H + t] = a;
    }
    __threadfence();
    __syncthreads();
    if (t == 0) {
        int tk = atomicAdd(&g_cnt[g], 1);
        s_flag[0] = (tk == 7);
    }
    __syncthreads();

    if (s_flag[0]) {
        __threadfence();
        if (t < H) {
            const float* pp = g_part + g * 8 * H + t;
            float p01 = pp[0] + pp[H];
            float p23 = pp[2*H] + pp[3*H];
            float p45 = pp[4*H] + pp[5*H];
            float p67 = pp[6*H] + pp[7*H];
            pooled[t] = ((p01 + p23) + (p45 + p67)) * (1.f / (float)TSB);
        }
        __syncthreads();
        if (t < 64) {
            float sv = __ldg(&b1[t]);
            #pragma unroll
            for (int i = 0; i < H; i++) sv += pooled[i] * __ldg(&w1[i * 64 + t]);
            h1s[t] = eluf(sv);
        }
        __syncthreads();
        if (t < 32) {
            float sv = __ldg(&b2[t]);
            #pragma unroll
            for (int i = 0; i < 64; i++) sv += h1s[i] * __ldg(&w2[i * 32 + t]);
            h2s[t] = eluf(sv);
        }
        __syncthreads();
        if (t < 8) {
            float sv = __ldg(&b3[t]);
            #pragma unroll
            for (int i = 0; i < 32; i++) sv += h2s[i] * __ldg(&w3[i * 8 + t]);
            h3s[t] = eluf(sv);
        }
        __syncthreads();
        if (t < 4) {
            float sv = __ldg(&b4[t]);
            #pragma unroll
            for (int i = 0; i < 8; i++) sv += h3s[i] * __ldg(&w4[i * 4 + t]);
            h4s[t] = eluf(sv);
        }
        __syncthreads();
        if (t == 0) {
            float sv = __ldg(&b5[0]);
            #pragma unroll
            for (int i = 0; i < 4; i++) sv += h4s[i] * __ldg(&w5[i]);
            if (g < out_size) out[g] = sv;
            if (NB + g < out_size) out[NB + g] = (float)g;
        }
    }
}

// ==================== launch ====================
extern "C" void kernel_launch(void* const* d_in, const int* in_sizes, int n_in,
                              void* d_out, int out_size)
{
    const float* x_ts = (const float*)d_in[0];
    const float* x_lc = (const float*)d_in[1];
    const float* tw1 = (const float*)d_in[4];
    const float* tb1 = (const float*)d_in[5];
    const float* tw2 = (const float*)d_in[6];
    const float* tb2 = (const float*)d_in[7];
    const float* lw1 = (const float*)d_in[8];
    const float* lb1 = (const float*)d_in[9];
    const float* lw2 = (const float*)d_in[10];
    const float* lb2 = (const float*)d_in[11];
    const float* cw  = (const float*)d_in[12];
    const float* cb  = (const float*)d_in[13];
    const float* w1  = (const float*)d_in[14];
    const float* b1  = (const float*)d_in[15];
    const float* w2  = (const float*)d_in[16];
    const float* b2  = (const float*)d_in[17];
    const float* w3  = (const float*)d_in[18];
    const float* b3  = (const float*)d_in[19];
    const float* w4  = (const float*)d_in[20];
    const float* b4  = (const float*)d_in[21];
    const float* w5  = (const float*)d_in[22];
    const float* b5  = (const float*)d_in[23];

    cudaFuncSetAttribute(kA, cudaFuncAttributeMaxDynamicSharedMemorySize, A_TOTF * 4);
    cudaFuncSetAttribute(kB, cudaFuncAttributeMaxDynamicSharedMemorySize, B_TOTF * 4);

    k_encode<<<(N_TS + N_LC) / 128, 128>>>(x_ts, x_lc, tw1, tb1, tw2, tb2,
                                           lw1, lb1, lw2, lb2, cw, cb);
    kA<<<NB * 10, 256, A_TOTF * 4>>>(cw, cb);
    kB<<<NB * 8, 128, B_TOTF * 4>>>(w1, b1, w2, b2, w3, b3, w4, b4, w5, b5,
                                    (float*)d_out, out_size);
}

// round 10
// speedup vs baseline: 2.2431x; 1.0413x over previous
#include <cuda_runtime.h>
#include <math.h>

#define N_TS 8192
#define N_LC 12288
#define NB   64
#define TSB  128
#define LCB  192
#define H    16
#define ROWP 20

// ---------------- global scratch ----------------
__device__ float g_ts_enc[N_TS * H];
__device__ float g_u_ts [N_TS * H];
__device__ float g_lc_enc[N_LC * H];
__device__ float g_u_lc [N_LC * H];
__device__ float g_v_lc [N_LC * H];
__device__ float g_nrm_lc[N_LC];
__device__ float g_f1  [N_LC * H];
__device__ float g_v3  [N_LC * H];
__device__ float g_nrm3[N_LC];
__device__ float g_f2  [N_TS * H];
__device__ float g_u3  [N_TS * H];
__device__ float g_part[NB * 8 * H];
__device__ int   g_cnt [NB];

__device__ __forceinline__ float eluf(float x) { return x > 0.f ? x : expm1f(x); }

__device__ __forceinline__ void ld16s(float (&x)[H], const float* p) {
    const float4* p4 = (const float4*)p;
    #pragma unroll
    for (int q = 0; q < 4; q++) {
        float4 v = p4[q];
        x[4*q] = v.x; x[4*q+1] = v.y; x[4*q+2] = v.z; x[4*q+3] = v.w;
    }
}
__device__ __forceinline__ void ld16g(float (&x)[H], const float* p) {
    const float4* p4 = (const float4*)p;
    #pragma unroll
    for (int q = 0; q < 4; q++) {
        float4 v = __ldg(&p4[q]);
        x[4*q] = v.x; x[4*q+1] = v.y; x[4*q+2] = v.z; x[4*q+3] = v.w;
    }
}

__device__ __forceinline__ float distf(const float (&xi)[H], float nd,
                                       const float* __restrict__ sp, float nj)
{
    const float4* p4 = (const float4*)sp;
    float4 p0 = p4[0], p1 = p4[1], p2 = p4[2], p3 = p4[3];
    float d0 = fmaf(xi[0],  p0.x, fmaf(xi[1],  p0.y, fmaf(xi[2],  p0.z, xi[3]  * p0.w)));
    float d1 = fmaf(xi[4],  p1.x, fmaf(xi[5],  p1.y, fmaf(xi[6],  p1.z, xi[7]  * p1.w)));
    float d2 = fmaf(xi[8],  p2.x, fmaf(xi[9],  p2.y, fmaf(xi[10], p2.z, xi[11] * p2.w)));
    float d3 = fmaf(xi[12], p3.x, fmaf(xi[13], p3.y, fmaf(xi[14], p3.z, xi[15] * p3.w)));
    float dot = __fadd_rn(__fadd_rn(d0, d1), __fadd_rn(d2, d3));
    return fmaf(-2.0f, dot, __fadd_rn(nd, nj));
}

__device__ __forceinline__ float norm16(const float (&x)[H]) {
    float n0 = fmaf(x[0],  x[0],  fmaf(x[1],  x[1],  fmaf(x[2],  x[2],  x[3]  * x[3])));
    float n1 = fmaf(x[4],  x[4],  fmaf(x[5],  x[5],  fmaf(x[6],  x[6],  x[7]  * x[7])));
    float n2 = fmaf(x[8],  x[8],  fmaf(x[9],  x[9],  fmaf(x[10], x[10], x[11] * x[11])));
    float n3 = fmaf(x[12], x[12], fmaf(x[13], x[13], fmaf(x[14], x[14], x[15] * x[15])));
    return (n0 + n1) + (n2 + n3);
}

__device__ __forceinline__ void bitonic16(float (&m)[16]) {
    #pragma unroll
    for (int j = 8; j > 0; j >>= 1) {
        #pragma unroll
        for (int i = 0; i < 16; i++) {
            if ((i & j) == 0) {
                float lo = fminf(m[i], m[i + j]);
                m[i + j] = fmaxf(m[i], m[i + j]);
                m[i] = lo;
            }
        }
    }
}

template<int NT>
__device__ __forceinline__ float pass1_T8(const float (&xi)[H], float nd,
                                          const float* __restrict__ s_enc,
                                          const float* __restrict__ s_nrm,
                                          float* __restrict__ s_d,
                                          int oct, int t)
{
    float bd[16];
    #pragma unroll
    for (int k = 0; k < 16; k++) bd[k] = 1e30f;
    #pragma unroll 2
    for (int j = 0; j < 24; j++) {
        int row = (j << 3) | oct;
        float d = distf(xi, nd, s_enc + row * ROWP, s_nrm[row]);
        s_d[j * NT + t] = d;
        #pragma unroll
        for (int k = 0; k < 16; k++) {
            float lo = fminf(d, bd[k]);
            d = fmaxf(d, bd[k]);
            bd[k] = lo;
        }
    }
    float m[16];
    #pragma unroll
    for (int k = 0; k < 16; k++)
        m[k] = fminf(bd[k], __shfl_xor_sync(0xFFFFFFFFu, bd[15 - k], 1));
    bitonic16(m);
    #pragma unroll
    for (int k = 0; k < 16; k++)
        bd[k] = fminf(m[k], __shfl_xor_sync(0xFFFFFFFFu, m[15 - k], 2));
    bitonic16(bd);
    float T = -1e30f;
    #pragma unroll
    for (int k = 0; k < 16; k++)
        T = fmaxf(T, fminf(bd[k], __shfl_xor_sync(0xFFFFFFFFu, bd[15 - k], 4)));
    return T;
}

template<int NT>
__device__ __forceinline__ void select_maxv8(float T,
                                             const float* __restrict__ s_d,
                                             const float* __restrict__ s_v,
                                             int* __restrict__ s_cnt,
                                             int* __restrict__ s_sel,
                                             int dl, int oct, int t, float (&mv)[H])
{
    #pragma unroll 4
    for (int j = 0; j < 24; j++) {
        float d = s_d[j * NT + t];
        if (d <= T) {
            int p = atomicAdd(&s_cnt[dl], 1);
            if (p < 24) s_sel[dl * 24 + p] = (j << 3) | oct;
        }
    }
    __syncwarp();
    #pragma unroll
    for (int h = 0; h < H; h++) mv[h] = -1e30f;
    int n = s_cnt[dl]; if (n > 24) n = 24;
    for (int k = oct; k < n; k += 8) {
        int row = s_sel[dl * 24 + k];
        const float4* v4 = (const float4*)(s_v + row * ROWP);
        float4 q0 = v4[0], q1 = v4[1], q2 = v4[2], q3 = v4[3];
        mv[0]  = fmaxf(mv[0],  q0.x); mv[1]  = fmaxf(mv[1],  q0.y);
        mv[2]  = fmaxf(mv[2],  q0.z); mv[3]  = fmaxf(mv[3],  q0.w);
        mv[4]  = fmaxf(mv[4],  q1.x); mv[5]  = fmaxf(mv[5],  q1.y);
        mv[6]  = fmaxf(mv[6],  q1.z); mv[7]  = fmaxf(mv[7],  q1.w);
        mv[8]  = fmaxf(mv[8],  q2.x); mv[9]  = fmaxf(mv[9],  q2.y);
        mv[10] = fmaxf(mv[10], q2.z); mv[11] = fmaxf(mv[11], q2.w);
        mv[12] = fmaxf(mv[12], q3.x); mv[13] = fmaxf(mv[13], q3.y);
        mv[14] = fmaxf(mv[14], q3.z); mv[15] = fmaxf(mv[15], q3.w);
    }
    #pragma unroll
    for (int h = 0; h < H; h++) mv[h] = fmaxf(mv[h], __shfl_xor_sync(0xFFFFFFFFu, mv[h], 1));
    #pragma unroll
    for (int h = 0; h < H; h++) mv[h] = fmaxf(mv[h], __shfl_xor_sync(0xFFFFFFFFu, mv[h], 2));
    #pragma unroll
    for (int h = 0; h < H; h++) mv[h] = fmaxf(mv[h], __shfl_xor_sync(0xFFFFFFFFu, mv[h], 4));
}

// ==================== K0: encoders — lane-per-channel, 2 points/warp ====================
// smem weight layout (floats):
//   0: tw1(96) | 96: tb1(16) | 112: tw2(256) | 368: tb2(16)
// 384: lw1(80) | 464: lb1(16)| 480: lw2(256) | 736: lb2(16)
// 752: cw(512) | 1264: cb(16)   total 1280 floats
__global__ void __launch_bounds__(256)
k_encode(const float* __restrict__ x_ts, const float* __restrict__ x_lc,
         const float* __restrict__ tw1, const float* __restrict__ tb1,
         const float* __restrict__ tw2, const float* __restrict__ tb2,
         const float* __restrict__ lw1, const float* __restrict__ lb1,
         const float* __restrict__ lw2, const float* __restrict__ lb2,
         const float* __restrict__ cw,  const float* __restrict__ cb)
{
    __shared__ float s_ew[1280];
    const int t = threadIdx.x;
    for (int i = t; i < 1280; i += 256) {
        float val;
        if      (i < 96)   val = __ldg(&tw1[i]);
        else if (i < 112)  val = __ldg(&tb1[i - 96]);
        else if (i < 368)  val = __ldg(&tw2[i - 112]);
        else if (i < 384)  val = __ldg(&tb2[i - 368]);
        else if (i < 464)  val = __ldg(&lw1[i - 384]);
        else if (i < 480)  val = __ldg(&lb1[i - 464]);
        else if (i < 736)  val = __ldg(&lw2[i - 480]);
        else if (i < 752)  val = __ldg(&lb2[i - 736]);
        else if (i < 1264) val = __ldg(&cw[i - 752]);
        else               val = __ldg(&cb[i - 1264]);
        s_ew[i] = val;
    }
    __syncthreads();

    const int gtid = blockIdx.x * 256 + t;
    const int p = gtid >> 4;        // point id (0..20479)
    const int o = gtid & 15;        // channel lane within the 16-group
    if (gtid < NB) g_cnt[gtid] = 0; // reset pool tickets for kB
    const unsigned FULL = 0xFFFFFFFFu;

    if (p < N_TS) {
        // ---- TS point: lanes 0..15 of the half-warp each own channel o ----
        float xv = (o < 6) ? __ldg(&x_ts[p * 6 + o]) : 0.f;
        float acc = s_ew[96 + o];
        #pragma unroll
        for (int i = 0; i < 6; i++)
            acc = fmaf(__shfl_sync(FULL, xv, i, 16), s_ew[i * H + o], acc);
        float h1 = eluf(acc);

        acc = s_ew[368 + o];
        #pragma unroll
        for (int i = 0; i < H; i++)
            acc = fmaf(__shfl_sync(FULL, h1, i, 16), s_ew[112 + i * H + o], acc);
        float e = eluf(acc);
        g_ts_enc[p * H + o] = e;

        float uacc = s_ew[1264 + o];
        #pragma unroll
        for (int i = 0; i < H; i++) {
            float ei = __shfl_sync(FULL, e, i, 16);
            uacc = fmaf(ei, s_ew[752 + i * H + o] - s_ew[752 + (H + i) * H + o], uacc);
        }
        g_u_ts[p * H + o] = uacc;
    } else if (p < N_TS + N_LC) {
        // ---- LC point ----
        const int id = p - N_TS;
        float xv = (o < 5) ? __ldg(&x_lc[id * 5 + o]) : 0.f;
        float acc = s_ew[464 + o];
        #pragma unroll
        for (int i = 0; i < 5; i++)
            acc = fmaf(__shfl_sync(FULL, xv, i, 16), s_ew[384 + i * H + o], acc);
        float h1 = eluf(acc);

        acc = s_ew[736 + o];
        #pragma unroll
        for (int i = 0; i < H; i++)
            acc = fmaf(__shfl_sync(FULL, h1, i, 16), s_ew[480 + i * H + o], acc);
        float e = eluf(acc);
        g_lc_enc[id * H + o] = e;

        // norm over the 16 lanes
        float r = e * e;
        r += __shfl_xor_sync(FULL, r, 1, 16);
        r += __shfl_xor_sync(FULL, r, 2, 16);
        r += __shfl_xor_sync(FULL, r, 4, 16);
        r += __shfl_xor_sync(FULL, r, 8, 16);
        if (o == 0) g_nrm_lc[id] = r;

        float uacc = s_ew[1264 + o], vacc = 0.f;
        #pragma unroll
        for (int i = 0; i < H; i++) {
            float ei = __shfl_sync(FULL, e, i, 16);
            float wt = s_ew[752 + i * H + o];
            float wb = s_ew[752 + (H + i) * H + o];
            uacc = fmaf(ei, wt - wb, uacc);
            vacc = fmaf(ei, wb, vacc);
        }
        g_u_lc[id * H + o] = uacc;
        g_v_lc[id * H + o] = vacc;
    }
}

// ================= kA: conv1 + conv2 (+u3/v3 fused), 32 dst x 8 thr =================
#define A_ENC 0
#define A_V   3840
#define A_NRM 7680
#define A_W   7872
#define A_B   8384
#define A_D   8400
#define A_F   14544
#define A_CNT 15184
#define A_SEL 15216
#define A_TOTF 15984   // 63936 bytes

__global__ void __launch_bounds__(256, 3)
kA(const float* __restrict__ cw, const float* __restrict__ cb)
{
    extern __shared__ float sm[];
    float* s_enc = sm + A_ENC;
    float* s_v   = sm + A_V;
    float* s_nrm = sm + A_NRM;
    float* s_w   = sm + A_W;
    float* s_b   = sm + A_B;
    float* s_d   = sm + A_D;
    float* s_f   = sm + A_F;
    int*   s_cnt = (int*)(sm + A_CNT);
    int*   s_sel = (int*)(sm + A_SEL);

    const int g = blockIdx.x / 10, part = blockIdx.x % 10;
    const int t = threadIdx.x;
    const bool isLC = part < 6;

    {
        const float4* ge = (const float4*)(g_lc_enc + g * LCB * H);
        const float4* gv = (const float4*)(g_v_lc  + g * LCB * H);
        float4* se = (float4*)s_enc; float4* sv = (float4*)s_v;
        #pragma unroll
        for (int i = t; i < LCB * 4; i += 256) {
            int r = i >> 2, c = i & 3;
            se[r * 5 + c] = __ldg(&ge[i]);
            sv[r * 5 + c] = __ldg(&gv[i]);
        }
        if (t < LCB) s_nrm[t] = __ldg(&g_nrm_lc[g * LCB + t]);
        for (int i = t; i < 512; i += 256) s_w[i] = __ldg(&cw[i]);
        if (t < 16) s_b[t] = __ldg(&cb[t]);
        if (t < 32) s_cnt[t] = 0;
    }
    __syncthreads();

    const int dl = t >> 3, oct = t & 7;
    const int dstRow = isLC ? g * LCB + part * 32 + dl
                            : g * TSB + (part - 6) * 32 + dl;
    float xi[H];
    if (isLC) ld16s(xi, s_enc + (part * 32 + dl) * ROWP);
    else      ld16g(xi, g_ts_enc + dstRow * H);
    float nd = norm16(xi);

    float T = pass1_T8<256>(xi, nd, s_enc, s_nrm, s_d, oct, t);
    float mv[H];
    select_maxv8<256>(T, s_d, s_v, s_cnt, s_sel, dl, oct, t, mv);

    const int ch0 = oct * 2;
    const float* uPtr = (isLC ? g_u_lc : g_u_ts) + dstRow * H;
    float u0 = __ldg(&uPtr[ch0]), u1 = __ldg(&uPtr[ch0 + 1]);
    float fa = eluf(u0 + mv[ch0]), fb = eluf(u1 + mv[ch0 + 1]);
    s_f[dl * ROWP + ch0] = fa; s_f[dl * ROWP + ch0 + 1] = fb;
    __syncwarp();
    float f[H];
    ld16s(f, s_f + dl * ROWP);

    if (isLC) {
        *(float2*)&g_f1[dstRow * H + ch0] = make_float2(fa, fb);
        float a0 = 0.f, a1 = 0.f;
        #pragma unroll
        for (int i = 0; i < H; i++) {
            a0 = fmaf(f[i], s_w[(H + i) * H + ch0], a0);
            a1 = fmaf(f[i], s_w[(H + i) * H + ch0 + 1], a1);
        }
        *(float2*)&g_v3[dstRow * H + ch0] = make_float2(a0, a1);
        if (oct == 0) g_nrm3[dstRow] = norm16(f);
    } else {
        *(float2*)&g_f2[dstRow * H + ch0] = make_float2(fa, fb);
        float a0 = s_b[ch0], a1 = s_b[ch0 + 1];
        #pragma unroll
        for (int i = 0; i < H; i++) {
            a0 = fmaf(f[i], s_w[i * H + ch0] - s_w[(H + i) * H + ch0], a0);
            a1 = fmaf(f[i], s_w[i * H + ch0 + 1] - s_w[(H + i) * H + ch0 + 1], a1);
        }
        *(float2*)&g_u3[dstRow * H + ch0] = make_float2(a0, a1);
    }
}

// ================= kB: conv3 + pool + head, 16 dst x 8 thr =================
#define B_ENC  0
#define B_V    3840
#define B_NRM  7680
#define B_D    7872
#define B_POOL 10944
#define B_PLD  11264
#define B_H1   11280
#define B_H2   11344
#define B_H3   11376
#define B_H4   11384
#define B_CNT  11388
#define B_SEL  11404
#define B_FLAG 11788
#define B_TOTF 11792   // 47168 bytes

__global__ void __launch_bounds__(128, 4)
kB(const float* __restrict__ w1, const float* __restrict__ b1,
   const float* __restrict__ w2, const float* __restrict__ b2,
   const float* __restrict__ w3, const float* __restrict__ b3,
   const float* __restrict__ w4, const float* __restrict__ b4,
   const float* __restrict__ w5, const float* __restrict__ b5,
   float* __restrict__ out, int out_size)
{
    extern __shared__ float sm[];
    float* s_enc  = sm + B_ENC;
    float* s_v    = sm + B_V;
    float* s_nrm  = sm + B_NRM;
    float* s_d    = sm + B_D;
    float* s_pool = sm + B_POOL;
    float* pooled = sm + B_PLD;
    float* h1s    = sm + B_H1;
    float* h2s    = sm + B_H2;
    float* h3s    = sm + B_H3;
    float* h4s    = sm + B_H4;
    int*   s_cnt  = (int*)(sm + B_CNT);
    int*   s_sel  = (int*)(sm + B_SEL);
    int*   s_flag = (int*)(sm + B_FLAG);

    const int g = blockIdx.x >> 3, qpart = blockIdx.x & 7;
    const int t = threadIdx.x;

    {
        const float4* ge = (const float4*)(g_f1 + g * LCB * H);
        const float4* gv = (const float4*)(g_v3 + g * LCB * H);
        float4* se = (float4*)s_enc; float4* sv = (float4*)s_v;
        #pragma unroll
        for (int i = t; i < LCB * 4; i += 128) {
            int r = i >> 2, c = i & 3;
            se[r * 5 + c] = __ldg(&ge[i]);
            sv[r * 5 + c] = __ldg(&gv[i]);
        }
        for (int i = t; i < LCB; i += 128) s_nrm[i] = __ldg(&g_nrm3[g * LCB + i]);
        if (t < 16) s_cnt[t] = 0;
    }
    __syncthreads();

    const int dl = t >> 3, oct = t & 7;
    const int dstRow = g * TSB + qpart * 16 + dl;
    float xi[H];
    ld16g(xi, g_f2 + dstRow * H);
    float nd = norm16(xi);

    float T = pass1_T8<128>(xi, nd, s_enc, s_nrm, s_d, oct, t);
    float mv[H];
    select_maxv8<128>(T, s_d, s_v, s_cnt, s_sel, dl, oct, t, mv);

    const int ch0 = oct * 2;
    float u0 = __ldg(&g_u3[dstRow * H + ch0]), u1 = __ldg(&g_u3[dstRow * H + ch0 + 1]);
    s_pool[dl * ROWP + ch0]     = eluf(u0 + mv[ch0]);
    s_pool[dl * ROWP + ch0 + 1] = eluf(u1 + mv[ch0 + 1]);
    __syncthreads();

    if (t < H) {
        float a = 0.f;
        #pragma unroll
        for (int d = 0; d < 16; d++) a += s_pool[d * ROWP + t];
        g_part[(g * 8 + qpart) * H + t] = a;
    }
    __threadfence();
    __syncthreads();
    if (t == 0) {
        int tk = atomicAdd(&g_cnt[g], 1);
        s_flag[0] = (tk == 7);
    }
    __syncthreads();

    if (s_flag[0]) {
        __threadfence();
        if (t < H) {
            const float* pp = g_part + g * 8 * H + t;
            float p01 = pp[0] + pp[H];
            float p23 = pp[2*H] + pp[3*H];
            float p45 = pp[4*H] + pp[5*H];
            float p67 = pp[6*H] + pp[7*H];
            pooled[t] = ((p01 + p23) + (p45 + p67)) * (1.f / (float)TSB);
        }
        __syncthreads();
        if (t < 64) {
            float sv = __ldg(&b1[t]);
            #pragma unroll
            for (int i = 0; i < H; i++) sv += pooled[i] * __ldg(&w1[i * 64 + t]);
            h1s[t] = eluf(sv);
        }
        __syncthreads();
        if (t < 32) {
            float sv = __ldg(&b2[t]);
            #pragma unroll
            for (int i = 0; i < 64; i++) sv += h1s[i] * __ldg(&w2[i * 32 + t]);
            h2s[t] = eluf(sv);
        }
        __syncthreads();
        if (t < 8) {
            float sv = __ldg(&b3[t]);
            #pragma unroll
            for (int i = 0; i < 32; i++) sv += h2s[i] * __ldg(&w3[i * 8 + t]);
            h3s[t] = eluf(sv);
        }
        __syncthreads();
        if (t < 4) {
            float sv = __ldg(&b4[t]);
            #pragma unroll
            for (int i = 0; i < 8; i++) sv += h3s[i] * __ldg(&w4[i * 4 + t]);
            h4s[t] = eluf(sv);
        }
        __syncthreads();
        if (t == 0) {
            float sv = __ldg(&b5[0]);
            #pragma unroll
            for (int i = 0; i < 4; i++) sv += h4s[i] * __ldg(&w5[i]);
            if (g < out_size) out[g] = sv;
            if (NB + g < out_size) out[NB + g] = (float)g;
        }
    }
}

// ==================== launch ====================
extern "C" void kernel_launch(void* const* d_in, const int* in_sizes, int n_in,
                              void* d_out, int out_size)
{
    const float* x_ts = (const float*)d_in[0];
    const float* x_lc = (const float*)d_in[1];
    const float* tw1 = (const float*)d_in[4];
    const float* tb1 = (const float*)d_in[5];
    const float* tw2 = (const float*)d_in[6];
    const float* tb2 = (const float*)d_in[7];
    const float* lw1 = (const float*)d_in[8];
    const float* lb1 = (const float*)d_in[9];
    const float* lw2 = (const float*)d_in[10];
    const float* lb2 = (const float*)d_in[11];
    const float* cw  = (const float*)d_in[12];
    const float* cb  = (const float*)d_in[13];
    const float* w1  = (const float*)d_in[14];
    const float* b1  = (const float*)d_in[15];
    const float* w2  = (const float*)d_in[16];
    const float* b2  = (const float*)d_in[17];
    const float* w3  = (const float*)d_in[18];
    const float* b3  = (const float*)d_in[19];
    const float* w4  = (const float*)d_in[20];
    const float* b4  = (const float*)d_in[21];
    const float* w5  = (const float*)d_in[22];
    const float* b5  = (const float*)d_in[23];

    cudaFuncSetAttribute(kA, cudaFuncAttributeMaxDynamicSharedMemorySize, A_TOTF * 4);
    cudaFuncSetAttribute(kB, cudaFuncAttributeMaxDynamicSharedMemorySize, B_TOTF * 4);

    // lane-per-channel encode: 16 threads per point
    k_encode<<<((N_TS + N_LC) * 16) / 256, 256>>>(x_ts, x_lc, tw1, tb1, tw2, tb2,
                                                  lw1, lb1, lw2, lb2, cw, cb);
    kA<<<NB * 10, 256, A_TOTF * 4>>>(cw, cb);
    kB<<<NB * 8, 128, B_TOTF * 4>>>(w1, b1, w2, b2, w3, b3, w4, b4, w5, b5,
                                    (float*)d_out, out_size);
}